// round 1
// baseline (speedup 1.0000x reference)
#include <cuda_runtime.h>

// ---------------- static device buffers (no runtime allocation allowed) -----
#define BUFSZ (1 << 19)

__device__ float g_h1[64 * 128 * 64 * 64];   // conv1 out
__device__ float g_h2[64 * 256 * 32 * 32];   // conv2 out
__device__ float g_h3[64 * 512 * 16 * 16];   // conv3 out
__device__ float g_pool[64 * 512];
__device__ float g_fc1[64 * 1024];

__device__ float g_mw1[128 * 3 * 9];
__device__ float g_mw2[256 * 128 * 9];
__device__ float g_mw3[512 * 256 * 9];
__device__ float g_mfw1[1024 * 512];
__device__ float g_mfw2[10 * 1024];

__device__ unsigned int       g_hist[2048];
__device__ int                g_cnt;
__device__ int                g_selbin;
__device__ int                g_selrank;
__device__ unsigned long long g_thresh;
__device__ unsigned long long g_bufA[BUFSZ];
__device__ unsigned long long g_bufB[BUFSZ];

// ---------------- mask selection: stable-sort-equivalent k-th key ----------
// key64 = (bits(|s|) << 32) | index   -> all keys unique, ascending order
// matches stable argsort of |s|. mask[i] = key64(i) >= (j-th smallest key64).

__global__ void reset_k() {
    int i = threadIdx.x;
    g_hist[i] = 0;
    g_hist[i + 1024] = 0;
    if (i == 0) g_cnt = 0;
}

__global__ void hist_k(const float* __restrict__ s, int n) {
    int i = blockIdx.x * blockDim.x + threadIdx.x;
    int stride = gridDim.x * blockDim.x;
    for (; i < n; i += stride) {
        unsigned int bits = __float_as_uint(s[i]) & 0x7fffffffu;
        atomicAdd(&g_hist[bits >> 21], 1u);
    }
}

__global__ void findbin_k(int j) {
    if (threadIdx.x == 0) {
        int cum = 0;
        for (int b = 0; b < 2048; b++) {
            int c = (int)g_hist[b];
            if (j < cum + c) { g_selbin = b; g_selrank = j - cum; break; }
            cum += c;
        }
    }
}

__global__ void compact_k(const float* __restrict__ s, int n) {
    int sb = g_selbin;
    int i = blockIdx.x * blockDim.x + threadIdx.x;
    int stride = gridDim.x * blockDim.x;
    for (; i < n; i += stride) {
        unsigned int bits = __float_as_uint(s[i]) & 0x7fffffffu;
        if ((int)(bits >> 21) == sb) {
            int p = atomicAdd(&g_cnt, 1);
            if (p < BUFSZ)
                g_bufA[p] = ((unsigned long long)bits << 32) | (unsigned int)i;
        }
    }
}

// single-block radix select over 64-bit keys (8 passes of 8 bits, compacting)
__global__ void select_k() {
    __shared__ int hist[256];
    __shared__ int s_m, s_r, s_d, s_cnt;
    int tid = threadIdx.x;
    if (tid == 0) {
        s_m = g_cnt < BUFSZ ? g_cnt : BUFSZ;
        s_r = g_selrank;
    }
    __syncthreads();
    unsigned long long* cur = g_bufA;
    unsigned long long* nxt = g_bufB;
    for (int shift = 56; shift >= 0; shift -= 8) {
        for (int b = tid; b < 256; b += blockDim.x) hist[b] = 0;
        __syncthreads();
        int m = s_m;
        for (int i = tid; i < m; i += blockDim.x)
            atomicAdd(&hist[(int)((cur[i] >> shift) & 255ull)], 1);
        __syncthreads();
        if (tid == 0) {
            int r = s_r, cum = 0;
            for (int d = 0; d < 256; d++) {
                int c = hist[d];
                if (r < cum + c) { s_d = d; s_r = r - cum; break; }
                cum += c;
            }
            s_cnt = 0;
        }
        __syncthreads();
        int d = s_d;
        for (int i = tid; i < m; i += blockDim.x) {
            unsigned long long v = cur[i];
            if ((int)((v >> shift) & 255ull) == d) {
                int p = atomicAdd(&s_cnt, 1);
                nxt[p] = v;
            }
        }
        __syncthreads();
        if (tid == 0) s_m = s_cnt;
        __syncthreads();
        unsigned long long* t = cur; cur = nxt; nxt = t;
    }
    if (tid == 0) g_thresh = cur[0];
}

__global__ void mask_k(const float* __restrict__ w, const float* __restrict__ s,
                       float* __restrict__ mw, int n) {
    unsigned long long th = g_thresh;
    int i = blockIdx.x * blockDim.x + threadIdx.x;
    int stride = gridDim.x * blockDim.x;
    for (; i < n; i += stride) {
        unsigned int bits = __float_as_uint(s[i]) & 0x7fffffffu;
        unsigned long long key = ((unsigned long long)bits << 32) | (unsigned int)i;
        mw[i] = (key >= th) ? w[i] : 0.0f;
    }
}

// ---------------- implicit-GEMM direct conv (fp32), fused bias+relu --------
// out[n][oc][oh][ow] = relu(b[oc] + sum_{ic,kh,kw} in[n][ic][oh*S-1+kh][ow*S-1+kw]
//                                                  * w[oc][ic*9+kh*3+kw])
// GEMM: M=OC (64/block), N=pixels (64/block), K=IC*9 (8/chunk); 4x4 per thread.
template <int S>
__global__ __launch_bounds__(256) void conv_k(
    const float* __restrict__ in, const float* __restrict__ w,
    const float* __restrict__ bias, float* __restrict__ out,
    int IC, int IH, int IW, int OC, int OH, int OW, int K) {
    __shared__ float As[8][68];   // stride 68: conflict-free, 16B aligned
    __shared__ float Bs[8][68];

    int tid = threadIdx.x;
    int tx = tid & 15, ty = tid >> 4;
    int pix0 = blockIdx.x * 64;
    int oc0 = blockIdx.y * 64;

    // B-load: fixed pixel per thread, two k rows (kkB, kkB+4)
    int nnB = tid & 63;
    int kkB = tid >> 6;
    int pixB = pix0 + nnB;
    int ohw = OH * OW;
    int nimg = pixB / ohw;
    int rem = pixB - nimg * ohw;
    int oh = rem / OW;
    int ow = rem - oh * OW;
    int ih0 = oh * S - 1;
    int iw0 = ow * S - 1;
    const float* inN = in + (long long)nimg * IC * IH * IW;
    int ihw = IH * IW;

    // A-load indices
    int kA = tid & 7;
    int mA = tid >> 3;

    float acc[4][4];
#pragma unroll
    for (int i = 0; i < 4; i++)
#pragma unroll
        for (int j = 0; j < 4; j++) acc[i][j] = 0.0f;

    for (int k0 = 0; k0 < K; k0 += 8) {
        {   // A tile: As[kk][m] = w[(oc0+m)*K + k0+kk]
            int kk = k0 + kA;
            float v0 = 0.0f, v1 = 0.0f;
            if (kk < K) {
                v0 = w[(oc0 + mA) * K + kk];
                v1 = w[(oc0 + mA + 32) * K + kk];
            }
            As[kA][mA] = v0;
            As[kA][mA + 32] = v1;
        }
#pragma unroll
        for (int u = 0; u < 2; u++) {   // B tile (im2col gather, zero padded)
            int kk = kkB + u * 4;
            int k = k0 + kk;
            float v = 0.0f;
            if (k < K) {
                int ic = k / 9;
                int r9 = k - ic * 9;
                int kh = r9 / 3;
                int kw = r9 - kh * 3;
                int ih = ih0 + kh, iw = iw0 + kw;
                if (ih >= 0 && ih < IH && iw >= 0 && iw < IW)
                    v = inN[ic * ihw + ih * IW + iw];
            }
            Bs[kk][nnB] = v;
        }
        __syncthreads();
#pragma unroll
        for (int kk = 0; kk < 8; kk++) {
            float4 a4 = *(const float4*)&As[kk][ty * 4];
            float4 b4 = *(const float4*)&Bs[kk][tx * 4];
            float a[4] = {a4.x, a4.y, a4.z, a4.w};
            float b[4] = {b4.x, b4.y, b4.z, b4.w};
#pragma unroll
            for (int i = 0; i < 4; i++)
#pragma unroll
                for (int j = 0; j < 4; j++) acc[i][j] += a[i] * b[j];
        }
        __syncthreads();
    }

#pragma unroll
    for (int i = 0; i < 4; i++) {
        int oc = oc0 + ty * 4 + i;
        float bv = bias[oc];
#pragma unroll
        for (int j = 0; j < 4; j++) {
            int pix = pix0 + tx * 4 + j;
            int n2 = pix / ohw;
            int r2 = pix - n2 * ohw;
            float v = acc[i][j] + bv;
            out[((long long)n2 * OC + oc) * ohw + r2] = v > 0.0f ? v : 0.0f;
        }
    }
}

// ---------------- pool + FC ------------------------------------------------
__global__ void pool_k(const float* __restrict__ in, float* __restrict__ out) {
    int warp = (blockIdx.x * blockDim.x + threadIdx.x) >> 5;
    int lane = threadIdx.x & 31;
    if (warp >= 64 * 512) return;
    const float* p = in + warp * 256;
    float s = 0.0f;
#pragma unroll
    for (int i = 0; i < 8; i++) s += p[lane + i * 32];
#pragma unroll
    for (int o = 16; o > 0; o >>= 1) s += __shfl_xor_sync(0xffffffffu, s, o);
    if (lane == 0) out[warp] = s * (1.0f / 256.0f);
}

__global__ void fc1_k(const float* __restrict__ inp, const float* __restrict__ w,
                      const float* __restrict__ b, float* __restrict__ out) {
    __shared__ float sx[512];
    int n = blockIdx.x;
    for (int i = threadIdx.x; i < 512; i += blockDim.x) sx[i] = inp[n * 512 + i];
    __syncthreads();
    int o = threadIdx.x;
    const float* wr = w + o * 512;
    float s = 0.0f;
#pragma unroll 8
    for (int k = 0; k < 512; k++) s += sx[k] * wr[k];
    s += b[o];
    out[n * 1024 + o] = s > 0.0f ? s : 0.0f;
}

__global__ void fc2_k(const float* __restrict__ inp, const float* __restrict__ w,
                      const float* __restrict__ b, float* __restrict__ out) {
    int idx = blockIdx.x * blockDim.x + threadIdx.x;
    if (idx >= 640) return;
    int n = idx / 10, o = idx - n * 10;
    const float* xr = inp + n * 1024;
    const float* wr = w + o * 1024;
    float s = 0.0f;
#pragma unroll 8
    for (int k = 0; k < 1024; k++) s += xr[k] * wr[k];
    out[idx] = s + b[o];
}

// ---------------- host orchestration ---------------------------------------
static inline int grid_for(int n) {
    int b = (n + 255) / 256;
    return b > 2048 ? 2048 : b;
}

static void run_select_and_mask(const float* w, const float* s, float* mw, int n) {
    int j = n / 2;  // int((1-0.5)*n), n even for all tensors here
    reset_k<<<1, 1024>>>();
    hist_k<<<grid_for(n), 256>>>(s, n);
    findbin_k<<<1, 32>>>(j);
    compact_k<<<grid_for(n), 256>>>(s, n);
    select_k<<<1, 1024>>>();
    mask_k<<<grid_for(n), 256>>>(w, s, mw, n);
}

extern "C" void kernel_launch(void* const* d_in, const int* in_sizes, int n_in,
                              void* d_out, int out_size) {
    const float* x   = (const float*)d_in[0];
    const float* w1  = (const float*)d_in[1];
    const float* s1  = (const float*)d_in[2];
    const float* b1  = (const float*)d_in[3];
    const float* w2  = (const float*)d_in[4];
    const float* s2  = (const float*)d_in[5];
    const float* b2  = (const float*)d_in[6];
    const float* w3  = (const float*)d_in[7];
    const float* s3  = (const float*)d_in[8];
    const float* b3  = (const float*)d_in[9];
    const float* fw1 = (const float*)d_in[10];
    const float* fs1 = (const float*)d_in[11];
    const float* fb1 = (const float*)d_in[12];
    const float* fw2 = (const float*)d_in[13];
    const float* fs2 = (const float*)d_in[14];
    const float* fb2 = (const float*)d_in[15];
    float* out = (float*)d_out;

    float *h1, *h2, *h3, *pool, *fc1o;
    float *mw1, *mw2, *mw3, *mfw1, *mfw2;
    cudaGetSymbolAddress((void**)&h1, g_h1);
    cudaGetSymbolAddress((void**)&h2, g_h2);
    cudaGetSymbolAddress((void**)&h3, g_h3);
    cudaGetSymbolAddress((void**)&pool, g_pool);
    cudaGetSymbolAddress((void**)&fc1o, g_fc1);
    cudaGetSymbolAddress((void**)&mw1, g_mw1);
    cudaGetSymbolAddress((void**)&mw2, g_mw2);
    cudaGetSymbolAddress((void**)&mw3, g_mw3);
    cudaGetSymbolAddress((void**)&mfw1, g_mfw1);
    cudaGetSymbolAddress((void**)&mfw2, g_mfw2);

    // masks (exact stable-argsort semantics via 64-bit keys)
    run_select_and_mask(w1,  s1,  mw1,  128 * 27);
    run_select_and_mask(w2,  s2,  mw2,  256 * 128 * 9);
    run_select_and_mask(w3,  s3,  mw3,  512 * 256 * 9);
    run_select_and_mask(fw1, fs1, mfw1, 1024 * 512);
    run_select_and_mask(fw2, fs2, mfw2, 10 * 1024);

    // conv1: [64,3,64,64] -> [64,128,64,64], stride 1
    {
        dim3 g(64 * 64 * 64 / 64, 128 / 64);
        conv_k<1><<<g, 256>>>(x, mw1, b1, h1, 3, 64, 64, 128, 64, 64, 27);
    }
    // conv2: -> [64,256,32,32], stride 2
    {
        dim3 g(64 * 32 * 32 / 64, 256 / 64);
        conv_k<2><<<g, 256>>>(h1, mw2, b2, h2, 128, 64, 64, 256, 32, 32, 128 * 9);
    }
    // conv3: -> [64,512,16,16], stride 2
    {
        dim3 g(64 * 16 * 16 / 64, 512 / 64);
        conv_k<2><<<g, 256>>>(h2, mw3, b3, h3, 256, 32, 32, 512, 16, 16, 256 * 9);
    }
    // global average pool -> [64,512]
    pool_k<<<(64 * 512) / 8, 256>>>(h3, pool);
    // fc1 -> [64,1024] relu
    fc1_k<<<64, 1024>>>(pool, mfw1, fb1, fc1o);
    // fc2 -> [64,10]
    fc2_k<<<3, 256>>>(fc1o, mfw2, fb2, out);
}

// round 4
// speedup vs baseline: 1.2117x; 1.2117x over previous
#include <cuda_runtime.h>

// ---------------- static device buffers (no runtime allocation allowed) -----
#define BUFSZ (1 << 19)

__device__ float g_h1[64 * 128 * 64 * 64];   // conv1 out
__device__ float g_h2[64 * 256 * 32 * 32];   // conv2 out
__device__ float g_h3[64 * 512 * 16 * 16];   // conv3 out
__device__ float g_pool[64 * 512];
__device__ float g_fc1[64 * 1024];

__device__ float g_mw1[128 * 3 * 9];
__device__ float g_mw2[256 * 128 * 9];
__device__ float g_mw3[512 * 256 * 9];
__device__ float g_mfw1[1024 * 512];
__device__ float g_mfw2[10 * 1024];

__device__ unsigned int       g_hist[2048];
__device__ int                g_cnt;
__device__ int                g_selbin;
__device__ int                g_selrank;
__device__ unsigned long long g_thresh;
__device__ unsigned long long g_bufA[BUFSZ];
__device__ unsigned long long g_bufB[BUFSZ];

// ---------------- packed f32x2 helpers -------------------------------------
#define FMA2(d, a, b, c) \
    asm("fma.rn.f32x2 %0, %1, %2, %3;" : "=l"(d) : "l"(a), "l"(b), "l"(c))
#define PACK2(out, lo, hi) \
    asm("mov.b64 %0, {%1, %2};" : "=l"(out) : "r"(lo), "r"(hi))
#define UNPACK2(lo, hi, in) \
    asm("mov.b64 {%0, %1}, %2;" : "=r"(lo), "=r"(hi) : "l"(in))

// ---------------- mask selection: stable-sort-equivalent k-th key ----------
// key64 = (bits(|s|) << 32) | index   -> all keys unique, ascending order
// matches stable argsort of |s|. mask[i] = key64(i) >= (j-th smallest key64).

__global__ void reset_k() {
    int i = threadIdx.x;
    g_hist[i] = 0;
    g_hist[i + 1024] = 0;
    if (i == 0) g_cnt = 0;
}

__global__ void hist_k(const float* __restrict__ s, int n) {
    int i = blockIdx.x * blockDim.x + threadIdx.x;
    int stride = gridDim.x * blockDim.x;
    for (; i < n; i += stride) {
        unsigned int bits = __float_as_uint(s[i]) & 0x7fffffffu;
        atomicAdd(&g_hist[bits >> 21], 1u);
    }
}

__global__ void findbin_k(int j) {
    if (threadIdx.x == 0) {
        int cum = 0;
        for (int b = 0; b < 2048; b++) {
            int c = (int)g_hist[b];
            if (j < cum + c) { g_selbin = b; g_selrank = j - cum; break; }
            cum += c;
        }
    }
}

__global__ void compact_k(const float* __restrict__ s, int n) {
    int sb = g_selbin;
    int i = blockIdx.x * blockDim.x + threadIdx.x;
    int stride = gridDim.x * blockDim.x;
    for (; i < n; i += stride) {
        unsigned int bits = __float_as_uint(s[i]) & 0x7fffffffu;
        if ((int)(bits >> 21) == sb) {
            int p = atomicAdd(&g_cnt, 1);
            if (p < BUFSZ)
                g_bufA[p] = ((unsigned long long)bits << 32) | (unsigned int)i;
        }
    }
}

// single-block radix select over 64-bit keys (8 passes of 8 bits, compacting)
__global__ void select_k() {
    __shared__ int hist[256];
    __shared__ int s_m, s_r, s_d, s_cnt;
    int tid = threadIdx.x;
    if (tid == 0) {
        s_m = g_cnt < BUFSZ ? g_cnt : BUFSZ;
        s_r = g_selrank;
    }
    __syncthreads();
    unsigned long long* cur = g_bufA;
    unsigned long long* nxt = g_bufB;
    for (int shift = 56; shift >= 0; shift -= 8) {
        for (int b = tid; b < 256; b += blockDim.x) hist[b] = 0;
        __syncthreads();
        int m = s_m;
        for (int i = tid; i < m; i += blockDim.x)
            atomicAdd(&hist[(int)((cur[i] >> shift) & 255ull)], 1);
        __syncthreads();
        if (tid == 0) {
            int r = s_r, cum = 0;
            for (int d = 0; d < 256; d++) {
                int c = hist[d];
                if (r < cum + c) { s_d = d; s_r = r - cum; break; }
                cum += c;
            }
            s_cnt = 0;
        }
        __syncthreads();
        int d = s_d;
        for (int i = tid; i < m; i += blockDim.x) {
            unsigned long long v = cur[i];
            if ((int)((v >> shift) & 255ull) == d) {
                int p = atomicAdd(&s_cnt, 1);
                nxt[p] = v;
            }
        }
        __syncthreads();
        if (tid == 0) s_m = s_cnt;
        __syncthreads();
        unsigned long long* t = cur; cur = nxt; nxt = t;
    }
    if (tid == 0) g_thresh = cur[0];
}

__global__ void mask_k(const float* __restrict__ w, const float* __restrict__ s,
                       float* __restrict__ mw, int n) {
    unsigned long long th = g_thresh;
    int i = blockIdx.x * blockDim.x + threadIdx.x;
    int stride = gridDim.x * blockDim.x;
    for (; i < n; i += stride) {
        unsigned int bits = __float_as_uint(s[i]) & 0x7fffffffu;
        unsigned long long key = ((unsigned long long)bits << 32) | (unsigned int)i;
        mw[i] = (key >= th) ? w[i] : 0.0f;
    }
}

// ---------------- implicit-GEMM conv, 128x128 tile, packed f32x2 FMA -------
// GEMM: M=OC (128/block), N=pixels (128/block), K=IC*9 (16/chunk).
// 256 threads, 8x8 outputs/thread; accumulators packed as f32x2 pairs over M
// so A operands come straight from smem as 64-bit pairs (no packing).
// Thread (tx,ty) owns rows {ty*4..+3, 64+ty*4..+3}, cols {tx*4..+3, 64+tx*4..+3}
// -> all LDS.128 conflict-free. Requires 128 | OH*OW (true for all 3 convs).
template <int S>
__global__ __launch_bounds__(256, 2) void conv128_k(
    const float* __restrict__ in, const float* __restrict__ w,
    const float* __restrict__ bias, float* __restrict__ out,
    int IC, int IH, int IW, int OC, int OH, int OW, int K) {
    __shared__ float As[16][132];   // row stride 132: 16B-aligned rows, conflict-free
    __shared__ float Bs[16][132];

    int tid = threadIdx.x;
    int tx = tid & 15, ty = tid >> 4;
    int pix0 = blockIdx.x * 128;
    int oc0 = blockIdx.y * 128;
    int ohw = OH * OW;
    int ihw = IH * IW;
    int nimg = pix0 / ohw;              // whole tile lives in one image
    int rem0 = pix0 - nimg * ohw;
    const float* inN = in + (long long)nimg * IC * ihw;

    // B-load mapping: pixel pB = tid&127, kk rows kkB0..kkB0+7
    int pB = tid & 127;
    int kkB0 = (tid >> 7) * 8;
    int remB = rem0 + pB;
    int oh = remB / OW, ow = remB - oh * OW;
    int ih0 = oh * S - 1, iw0 = ow * S - 1;

    // A-load mapping: kA = tid&15, rows mA, mA+16, ... (8 passes)
    int kA = tid & 15;
    int mA = tid >> 4;

    unsigned long long acc[4][8];
#pragma unroll
    for (int i = 0; i < 4; i++)
#pragma unroll
        for (int j = 0; j < 8; j++) acc[i][j] = 0ull;

    for (int k0 = 0; k0 < K; k0 += 16) {
        {   // A tile: As[kk][m] = w[(oc0+m)*K + k0+kk]
            int k = k0 + kA;
            bool kin = (k < K);
#pragma unroll
            for (int u = 0; u < 8; u++) {
                int m = mA + u * 16;
                As[kA][m] = kin ? w[(oc0 + m) * K + k] : 0.0f;
            }
        }
#pragma unroll
        for (int u = 0; u < 8; u++) {   // B tile (im2col gather, zero padded)
            int kk = kkB0 + u;
            int k = k0 + kk;
            float v = 0.0f;
            if (k < K) {
                int ic = k / 9;
                int r9 = k - ic * 9;
                int kh = r9 / 3;
                int kw = r9 - kh * 3;
                int ih = ih0 + kh, iw = iw0 + kw;
                if (ih >= 0 && ih < IH && iw >= 0 && iw < IW)
                    v = inN[ic * ihw + ih * IW + iw];
            }
            Bs[kk][pB] = v;
        }
        __syncthreads();
#pragma unroll
        for (int kk = 0; kk < 16; kk++) {
            // A: 4 packed pairs over M, loaded directly as 64-bit lanes
            ulonglong2 a01 = *(const ulonglong2*)&As[kk][ty * 4];
            ulonglong2 a23 = *(const ulonglong2*)&As[kk][64 + ty * 4];
            unsigned long long ap[4] = {a01.x, a01.y, a23.x, a23.y};
            // B: 8 scalars -> 8 broadcast pairs
            float4 bA = *(const float4*)&Bs[kk][tx * 4];
            float4 bB = *(const float4*)&Bs[kk][64 + tx * 4];
            float bs[8] = {bA.x, bA.y, bA.z, bA.w, bB.x, bB.y, bB.z, bB.w};
            unsigned long long bb[8];
#pragma unroll
            for (int j = 0; j < 8; j++)
                PACK2(bb[j], __float_as_uint(bs[j]), __float_as_uint(bs[j]));
#pragma unroll
            for (int i = 0; i < 4; i++)
#pragma unroll
                for (int j = 0; j < 8; j++)
                    FMA2(acc[i][j], ap[i], bb[j], acc[i][j]);
        }
        __syncthreads();
    }

    // epilogue: unpack pairs (lo = even row, hi = odd row), bias+relu, float4 st
    float* outB = out + ((long long)nimg * OC + oc0) * ohw + rem0;
    int mrow[4] = {ty * 4, ty * 4 + 2, 64 + ty * 4, 64 + ty * 4 + 2};
#pragma unroll
    for (int i = 0; i < 4; i++) {
        int me = mrow[i];
        float be = bias[oc0 + me];
        float bo = bias[oc0 + me + 1];
        float* pe = outB + (long long)me * ohw;
        float* po = outB + (long long)(me + 1) * ohw;
#pragma unroll
        for (int g = 0; g < 2; g++) {
            float4 ve, vo;
            unsigned int lo, hi;
            UNPACK2(lo, hi, acc[i][g * 4 + 0]); ve.x = __uint_as_float(lo); vo.x = __uint_as_float(hi);
            UNPACK2(lo, hi, acc[i][g * 4 + 1]); ve.y = __uint_as_float(lo); vo.y = __uint_as_float(hi);
            UNPACK2(lo, hi, acc[i][g * 4 + 2]); ve.z = __uint_as_float(lo); vo.z = __uint_as_float(hi);
            UNPACK2(lo, hi, acc[i][g * 4 + 3]); ve.w = __uint_as_float(lo); vo.w = __uint_as_float(hi);
            ve.x = fmaxf(ve.x + be, 0.0f); ve.y = fmaxf(ve.y + be, 0.0f);
            ve.z = fmaxf(ve.z + be, 0.0f); ve.w = fmaxf(ve.w + be, 0.0f);
            vo.x = fmaxf(vo.x + bo, 0.0f); vo.y = fmaxf(vo.y + bo, 0.0f);
            vo.z = fmaxf(vo.z + bo, 0.0f); vo.w = fmaxf(vo.w + bo, 0.0f);
            int off = tx * 4 + g * 64;
            *(float4*)(pe + off) = ve;
            *(float4*)(po + off) = vo;
        }
    }
}

// ---------------- pool + FC ------------------------------------------------
__global__ void pool_k(const float* __restrict__ in, float* __restrict__ out) {
    int warp = (blockIdx.x * blockDim.x + threadIdx.x) >> 5;
    int lane = threadIdx.x & 31;
    if (warp >= 64 * 512) return;
    const float* p = in + warp * 256;
    float s = 0.0f;
#pragma unroll
    for (int i = 0; i < 8; i++) s += p[lane + i * 32];
#pragma unroll
    for (int o = 16; o > 0; o >>= 1) s += __shfl_xor_sync(0xffffffffu, s, o);
    if (lane == 0) out[warp] = s * (1.0f / 256.0f);
}

__global__ void fc1_k(const float* __restrict__ inp, const float* __restrict__ w,
                      const float* __restrict__ b, float* __restrict__ out) {
    __shared__ float sx[512];
    int n = blockIdx.x;
    for (int i = threadIdx.x; i < 512; i += blockDim.x) sx[i] = inp[n * 512 + i];
    __syncthreads();
    int o = threadIdx.x;
    const float* wr = w + o * 512;
    float s = 0.0f;
#pragma unroll 8
    for (int k = 0; k < 512; k++) s += sx[k] * wr[k];
    s += b[o];
    out[n * 1024 + o] = s > 0.0f ? s : 0.0f;
}

__global__ void fc2_k(const float* __restrict__ inp, const float* __restrict__ w,
                      const float* __restrict__ b, float* __restrict__ out) {
    int idx = blockIdx.x * blockDim.x + threadIdx.x;
    if (idx >= 640) return;
    int n = idx / 10, o = idx - n * 10;
    const float* xr = inp + n * 1024;
    const float* wr = w + o * 1024;
    float s = 0.0f;
#pragma unroll 8
    for (int k = 0; k < 1024; k++) s += xr[k] * wr[k];
    out[idx] = s + b[o];
}

// ---------------- host orchestration ---------------------------------------
static inline int grid_for(int n) {
    int b = (n + 255) / 256;
    return b > 2048 ? 2048 : b;
}

static void run_select_and_mask(const float* w, const float* s, float* mw, int n) {
    int j = n / 2;  // int((1-0.5)*n), n even for all tensors here
    reset_k<<<1, 1024>>>();
    hist_k<<<grid_for(n), 256>>>(s, n);
    findbin_k<<<1, 32>>>(j);
    compact_k<<<grid_for(n), 256>>>(s, n);
    select_k<<<1, 1024>>>();
    mask_k<<<grid_for(n), 256>>>(w, s, mw, n);
}

extern "C" void kernel_launch(void* const* d_in, const int* in_sizes, int n_in,
                              void* d_out, int out_size) {
    const float* x   = (const float*)d_in[0];
    const float* w1  = (const float*)d_in[1];
    const float* s1  = (const float*)d_in[2];
    const float* b1  = (const float*)d_in[3];
    const float* w2  = (const float*)d_in[4];
    const float* s2  = (const float*)d_in[5];
    const float* b2  = (const float*)d_in[6];
    const float* w3  = (const float*)d_in[7];
    const float* s3  = (const float*)d_in[8];
    const float* b3  = (const float*)d_in[9];
    const float* fw1 = (const float*)d_in[10];
    const float* fs1 = (const float*)d_in[11];
    const float* fb1 = (const float*)d_in[12];
    const float* fw2 = (const float*)d_in[13];
    const float* fs2 = (const float*)d_in[14];
    const float* fb2 = (const float*)d_in[15];
    float* out = (float*)d_out;

    float *h1, *h2, *h3, *pool, *fc1o;
    float *mw1, *mw2, *mw3, *mfw1, *mfw2;
    cudaGetSymbolAddress((void**)&h1, g_h1);
    cudaGetSymbolAddress((void**)&h2, g_h2);
    cudaGetSymbolAddress((void**)&h3, g_h3);
    cudaGetSymbolAddress((void**)&pool, g_pool);
    cudaGetSymbolAddress((void**)&fc1o, g_fc1);
    cudaGetSymbolAddress((void**)&mw1, g_mw1);
    cudaGetSymbolAddress((void**)&mw2, g_mw2);
    cudaGetSymbolAddress((void**)&mw3, g_mw3);
    cudaGetSymbolAddress((void**)&mfw1, g_mfw1);
    cudaGetSymbolAddress((void**)&mfw2, g_mfw2);

    // masks (exact stable-argsort semantics via 64-bit keys)
    run_select_and_mask(w1,  s1,  mw1,  128 * 27);
    run_select_and_mask(w2,  s2,  mw2,  256 * 128 * 9);
    run_select_and_mask(w3,  s3,  mw3,  512 * 256 * 9);
    run_select_and_mask(fw1, fs1, mfw1, 1024 * 512);
    run_select_and_mask(fw2, fs2, mfw2, 10 * 1024);

    // conv1: [64,3,64,64] -> [64,128,64,64], stride 1
    {
        dim3 g(64 * 64 * 64 / 128, 1);
        conv128_k<1><<<g, 256>>>(x, mw1, b1, h1, 3, 64, 64, 128, 64, 64, 27);
    }
    // conv2: -> [64,256,32,32], stride 2
    {
        dim3 g(64 * 32 * 32 / 128, 2);
        conv128_k<2><<<g, 256>>>(h1, mw2, b2, h2, 128, 64, 64, 256, 32, 32, 128 * 9);
    }
    // conv3: -> [64,512,16,16], stride 2
    {
        dim3 g(64 * 16 * 16 / 128, 4);
        conv128_k<2><<<g, 256>>>(h2, mw3, b3, h3, 256, 32, 32, 512, 16, 16, 256 * 9);
    }
    // global average pool -> [64,512]
    pool_k<<<(64 * 512) / 8, 256>>>(h3, pool);
    // fc1 -> [64,1024] relu
    fc1_k<<<64, 1024>>>(pool, mfw1, fb1, fc1o);
    // fc2 -> [64,10]
    fc2_k<<<3, 256>>>(fc1o, mfw2, fb2, out);
}

// round 8
// speedup vs baseline: 1.9811x; 1.6349x over previous
#include <cuda_runtime.h>
#include <cuda_bf16.h>
#include <cstdint>

// ---------------- static device buffers (no runtime allocation allowed) -----
#define BUFSZ (1 << 19)

__device__ __align__(16) uint32_t g_h1p[64 * 128 * 64 * 64]; // conv1 out, packed (lo<<16|hi) bf16
__device__ __align__(16) uint32_t g_h2p[64 * 256 * 32 * 32]; // conv2 out, packed
__device__ float g_h3[64 * 512 * 16 * 16];                   // conv3 out fp32
__device__ float g_pool[64 * 512];
__device__ float g_fc1[64 * 1024];

__device__ float g_mw1[128 * 3 * 9];                         // conv1 masked fp32
__device__ __align__(16) uint32_t g_mw2p[256 * 128 * 9];     // masked+reordered+packed
__device__ __align__(16) uint32_t g_mw3p[512 * 256 * 9];
__device__ float g_mfw1[1024 * 512];
__device__ float g_mfw2[10 * 1024];

__device__ unsigned int       g_hist[2048];
__device__ int                g_cnt;
__device__ int                g_selbin;
__device__ int                g_selrank;
__device__ unsigned long long g_thresh;
__device__ unsigned long long g_bufA[BUFSZ];
__device__ unsigned long long g_bufB[BUFSZ];

// ---------------- packed f32x2 helpers (SIMT conv1) -------------------------
#define FMA2(d, a, b, c) \
    asm("fma.rn.f32x2 %0, %1, %2, %3;" : "=l"(d) : "l"(a), "l"(b), "l"(c))
#define PACK2(out, lo, hi) \
    asm("mov.b64 %0, {%1, %2};" : "=l"(out) : "r"(lo), "r"(hi))
#define UNPACK2(lo, hi, in) \
    asm("mov.b64 {%0, %1}, %2;" : "=r"(lo), "=r"(hi) : "l"(in))

// split fp32 -> packed word (lo16<<16)|hi16, bf16 hi + bf16 residual lo
__device__ __forceinline__ uint32_t packsplit(float v) {
    __nv_bfloat16 h = __float2bfloat16(v);
    float hf = __bfloat162float(h);
    __nv_bfloat16 l = __float2bfloat16(v - hf);
    uint16_t hb = *(uint16_t*)&h;
    uint16_t lb = *(uint16_t*)&l;
    return ((uint32_t)lb << 16) | (uint32_t)hb;
}

// ---------------- HMMA helpers ---------------------------------------------
__device__ __forceinline__ uint32_t smem_u32(const void* p) {
    uint32_t a;
    asm("{ .reg .u64 t; cvta.to.shared.u64 t, %1; cvt.u32.u64 %0, t; }"
        : "=r"(a) : "l"(p));
    return a;
}

__device__ __forceinline__ void ldm_x4(uint32_t* r, uint32_t addr) {
    asm volatile("ldmatrix.sync.aligned.m8n8.x4.shared.b16 {%0,%1,%2,%3}, [%4];"
                 : "=r"(r[0]), "=r"(r[1]), "=r"(r[2]), "=r"(r[3]) : "r"(addr));
}

__device__ __forceinline__ void mma_bf16(float* c, const uint32_t* a,
                                         const uint32_t* b) {
    asm volatile(
        "mma.sync.aligned.m16n8k16.row.col.f32.bf16.bf16.f32 "
        "{%0,%1,%2,%3}, {%4,%5,%6,%7}, {%8,%9}, {%0,%1,%2,%3};"
        : "+f"(c[0]), "+f"(c[1]), "+f"(c[2]), "+f"(c[3])
        : "r"(a[0]), "r"(a[1]), "r"(a[2]), "r"(a[3]), "r"(b[0]), "r"(b[1]));
}

// ---------------- mask selection: stable-sort-equivalent k-th key ----------
__global__ void reset_k() {
    int i = threadIdx.x;
    g_hist[i] = 0;
    g_hist[i + 1024] = 0;
    if (i == 0) g_cnt = 0;
}

__global__ void hist_k(const float* __restrict__ s, int n) {
    int i = blockIdx.x * blockDim.x + threadIdx.x;
    int stride = gridDim.x * blockDim.x;
    for (; i < n; i += stride) {
        unsigned int bits = __float_as_uint(s[i]) & 0x7fffffffu;
        atomicAdd(&g_hist[bits >> 21], 1u);
    }
}

__global__ void findbin_k(int j) {
    if (threadIdx.x == 0) {
        int cum = 0;
        for (int b = 0; b < 2048; b++) {
            int c = (int)g_hist[b];
            if (j < cum + c) { g_selbin = b; g_selrank = j - cum; break; }
            cum += c;
        }
    }
}

__global__ void compact_k(const float* __restrict__ s, int n) {
    int sb = g_selbin;
    int i = blockIdx.x * blockDim.x + threadIdx.x;
    int stride = gridDim.x * blockDim.x;
    for (; i < n; i += stride) {
        unsigned int bits = __float_as_uint(s[i]) & 0x7fffffffu;
        if ((int)(bits >> 21) == sb) {
            int p = atomicAdd(&g_cnt, 1);
            if (p < BUFSZ)
                g_bufA[p] = ((unsigned long long)bits << 32) | (unsigned int)i;
        }
    }
}

__global__ void select_k() {
    __shared__ int hist[256];
    __shared__ int s_m, s_r, s_d, s_cnt;
    int tid = threadIdx.x;
    if (tid == 0) {
        s_m = g_cnt < BUFSZ ? g_cnt : BUFSZ;
        s_r = g_selrank;
    }
    __syncthreads();
    unsigned long long* cur = g_bufA;
    unsigned long long* nxt = g_bufB;
    for (int shift = 56; shift >= 0; shift -= 8) {
        for (int b = tid; b < 256; b += blockDim.x) hist[b] = 0;
        __syncthreads();
        int m = s_m;
        for (int i = tid; i < m; i += blockDim.x)
            atomicAdd(&hist[(int)((cur[i] >> shift) & 255ull)], 1);
        __syncthreads();
        if (tid == 0) {
            int r = s_r, cum = 0;
            for (int d = 0; d < 256; d++) {
                int c = hist[d];
                if (r < cum + c) { s_d = d; s_r = r - cum; break; }
                cum += c;
            }
            s_cnt = 0;
        }
        __syncthreads();
        int d = s_d;
        for (int i = tid; i < m; i += blockDim.x) {
            unsigned long long v = cur[i];
            if ((int)((v >> shift) & 255ull) == d) {
                int p = atomicAdd(&s_cnt, 1);
                nxt[p] = v;
            }
        }
        __syncthreads();
        if (tid == 0) s_m = s_cnt;
        __syncthreads();
        unsigned long long* t = cur; cur = nxt; nxt = t;
    }
    if (tid == 0) g_thresh = cur[0];
}

__global__ void mask_k(const float* __restrict__ w, const float* __restrict__ s,
                       float* __restrict__ mw, int n) {
    unsigned long long th = g_thresh;
    int i = blockIdx.x * blockDim.x + threadIdx.x;
    int stride = gridDim.x * blockDim.x;
    for (; i < n; i += stride) {
        unsigned int bits = __float_as_uint(s[i]) & 0x7fffffffu;
        unsigned long long key = ((unsigned long long)bits << 32) | (unsigned int)i;
        mw[i] = (key >= th) ? w[i] : 0.0f;
    }
}

// mask + reorder k -> tap*IC+ic + split-pack for HMMA convs
__global__ void mask_pack_k(const float* __restrict__ w, const float* __restrict__ s,
                            uint32_t* __restrict__ outp, int IC, int n) {
    unsigned long long th = g_thresh;
    int K = IC * 9;
    int i = blockIdx.x * blockDim.x + threadIdx.x;
    int stride = gridDim.x * blockDim.x;
    for (; i < n; i += stride) {
        unsigned int bits = __float_as_uint(s[i]) & 0x7fffffffu;
        unsigned long long key = ((unsigned long long)bits << 32) | (unsigned int)i;
        float v = (key >= th) ? w[i] : 0.0f;
        int oc = i / K;
        int r = i - oc * K;
        int ic = r / 9;
        int tap = r - ic * 9;
        outp[oc * K + tap * IC + ic] = packsplit(v);
    }
}

// ---------------- HMMA conv (conv2/conv3) ----------------------------------
// D[oc, pix] = sum_k' W[oc,k'] * im2col[pix,k'], k' = tap*IC + ic (tap-major).
// BM=256, BN=128 pixels, BK=32 (one tap per chunk). 512 threads = 16 warps,
// warp (mg=w&3, ng=w>>2) owns m64 x n32. 3 bf16 MMAs: hi*hi + hi*lo + lo*hi.
#define CBM 256
#define CBN 128
#define CBK 32
#define ROWB 80
#define SM_AH 0
#define SM_AL (CBM * ROWB)
#define SM_BH (2 * CBM * ROWB)
#define SM_BL (2 * CBM * ROWB + CBN * ROWB)
#define SM_CONV (2 * CBM * ROWB + 2 * CBN * ROWB)   // 61440

template <int S, bool PACKOUT>
__global__ __launch_bounds__(512, 1) void conv_mma_k(
    const uint32_t* __restrict__ in, const uint32_t* __restrict__ wp,
    const float* __restrict__ bias, void* __restrict__ outv,
    int IC, int IH, int IW, int OCt, int OH, int OW, int K) {
    extern __shared__ char smem[];
    uint32_t sm = smem_u32(smem);
    int tid = threadIdx.x;
    int wid = tid >> 5, lane = tid & 31;

    int pix0 = blockIdx.x * CBN;
    int oc0 = blockIdx.y * CBM;
    int ohw = OH * OW;
    int ihw = IH * IW;
    int nimg = pix0 / ohw;             // 128 | ohw
    int rem0 = pix0 - nimg * ohw;
    const uint32_t* inN = in + (long long)nimg * IC * ihw;

    int ocA = tid >> 1;
    int halfA = tid & 1;
    int pB = tid & 127;
    int icj = (tid >> 7) * 8;
    int remB = rem0 + pB;
    int oh = remB / OW, ow = remB - oh * OW;
    int ih0 = oh * S - 1, iw0 = ow * S - 1;

    int mg = wid & 3, ng = wid >> 2;

    float acc[4][4][4];
#pragma unroll
    for (int a = 0; a < 4; a++)
#pragma unroll
        for (int b = 0; b < 4; b++)
#pragma unroll
            for (int c = 0; c < 4; c++) acc[a][b][c] = 0.0f;

    for (int k0 = 0; k0 < K; k0 += CBK) {
        // ---- A tile: 16 packed words/thread -> hi/lo halves into smem
        {
            // FIX (R7 bug): weight row must include the block's oc0 offset.
            const uint4* src =
                (const uint4*)(wp + (long long)(oc0 + ocA) * K + k0) + halfA * 4;
            uint32_t arow = sm + SM_AH + ocA * ROWB + halfA * 32;
            uint32_t lrow = arow + (SM_AL - SM_AH);
#pragma unroll
            for (int q = 0; q < 4; q++) {
                uint4 v = src[q];
                uint32_t h01 = __byte_perm(v.x, v.y, 0x5410);
                uint32_t l01 = __byte_perm(v.x, v.y, 0x7632);
                uint32_t h23 = __byte_perm(v.z, v.w, 0x5410);
                uint32_t l23 = __byte_perm(v.z, v.w, 0x7632);
                asm volatile("st.shared.v2.b32 [%0], {%1,%2};"
                             :: "r"(arow + q * 8), "r"(h01), "r"(h23) : "memory");
                asm volatile("st.shared.v2.b32 [%0], {%1,%2};"
                             :: "r"(lrow + q * 8), "r"(l01), "r"(l23) : "memory");
            }
        }
        // ---- B tile: tap fixed for this chunk; 8 strided loads/thread
        {
            int tap = k0 / IC;
            int icoff = k0 - tap * IC;
            int kh = tap / 3;
            int kw = tap - kh * 3;
            int ih = ih0 + kh, iw = iw0 + kw;
            bool valid = (ih >= 0 && ih < IH && iw >= 0 && iw < IW);
            uint32_t wv[8];
            if (valid) {
                const uint32_t* p = inN + (icoff + icj) * ihw + ih * IW + iw;
#pragma unroll
                for (int j = 0; j < 8; j++) { wv[j] = *p; p += ihw; }
            } else {
#pragma unroll
                for (int j = 0; j < 8; j++) wv[j] = 0u;
            }
            uint32_t brow = sm + SM_BH + pB * ROWB + icj * 2;
            uint32_t blrow = brow + (SM_BL - SM_BH);
#pragma unroll
            for (int j = 0; j < 8; j += 4) {
                uint32_t h01 = __byte_perm(wv[j], wv[j + 1], 0x5410);
                uint32_t l01 = __byte_perm(wv[j], wv[j + 1], 0x7632);
                uint32_t h23 = __byte_perm(wv[j + 2], wv[j + 3], 0x5410);
                uint32_t l23 = __byte_perm(wv[j + 2], wv[j + 3], 0x7632);
                asm volatile("st.shared.v2.b32 [%0], {%1,%2};"
                             :: "r"(brow + j * 2), "r"(h01), "r"(h23) : "memory");
                asm volatile("st.shared.v2.b32 [%0], {%1,%2};"
                             :: "r"(blrow + j * 2), "r"(l01), "r"(l23) : "memory");
            }
        }
        __syncthreads();

        // ---- MMA: 2 k16 steps
#pragma unroll
        for (int s = 0; s < 2; s++) {
            uint32_t bh[4][2], bl[4][2];
#pragma unroll
            for (int p = 0; p < 2; p++) {
                int row = ng * 32 + p * 16 + (lane & 7) + ((lane >> 4) & 1) * 8;
                int col = s * 16 + ((lane >> 3) & 1) * 8;
                uint32_t addr = sm + SM_BH + row * ROWB + col * 2;
                uint32_t r[4];
                ldm_x4(r, addr);
                bh[p * 2][0] = r[0]; bh[p * 2][1] = r[1];
                bh[p * 2 + 1][0] = r[2]; bh[p * 2 + 1][1] = r[3];
                ldm_x4(r, addr + (SM_BL - SM_BH));
                bl[p * 2][0] = r[0]; bl[p * 2][1] = r[1];
                bl[p * 2 + 1][0] = r[2]; bl[p * 2 + 1][1] = r[3];
            }
#pragma unroll
            for (int mb = 0; mb < 4; mb++) {
                int row = mg * 64 + mb * 16 + (lane & 15);
                int col = s * 16 + (lane >> 4) * 8;
                uint32_t addr = sm + SM_AH + row * ROWB + col * 2;
                uint32_t ah[4], al[4];
                ldm_x4(ah, addr);
                ldm_x4(al, addr + (SM_AL - SM_AH));
#pragma unroll
                for (int nb = 0; nb < 4; nb++) {
                    mma_bf16(acc[mb][nb], ah, bh[nb]);
                    mma_bf16(acc[mb][nb], ah, bl[nb]);
                    mma_bf16(acc[mb][nb], al, bh[nb]);
                }
            }
        }
        __syncthreads();
    }

    // ---- epilogue: bias + relu, write packed or fp32
    long long outbase = ((long long)nimg * OCt + oc0) * ohw + rem0;
#pragma unroll
    for (int mb = 0; mb < 4; mb++) {
        int r0 = mg * 64 + mb * 16 + (lane >> 2);
        int r1 = r0 + 8;
        float bv0 = bias[oc0 + r0];
        float bv1 = bias[oc0 + r1];
#pragma unroll
        for (int nb = 0; nb < 4; nb++) {
            int n = ng * 32 + nb * 8 + 2 * (lane & 3);
            float v00 = fmaxf(acc[mb][nb][0] + bv0, 0.0f);
            float v01 = fmaxf(acc[mb][nb][1] + bv0, 0.0f);
            float v10 = fmaxf(acc[mb][nb][2] + bv1, 0.0f);
            float v11 = fmaxf(acc[mb][nb][3] + bv1, 0.0f);
            if (PACKOUT) {
                uint32_t* o = (uint32_t*)outv;
                *(uint2*)(o + outbase + (long long)r0 * ohw + n) =
                    make_uint2(packsplit(v00), packsplit(v01));
                *(uint2*)(o + outbase + (long long)r1 * ohw + n) =
                    make_uint2(packsplit(v10), packsplit(v11));
            } else {
                float* o = (float*)outv;
                *(float2*)(o + outbase + (long long)r0 * ohw + n) = make_float2(v00, v01);
                *(float2*)(o + outbase + (long long)r1 * ohw + n) = make_float2(v10, v11);
            }
        }
    }
}

// ---------------- SIMT conv1, 128x128 tile, packed f32x2 FMA, packed out ----
template <int S>
__global__ __launch_bounds__(256, 2) void conv128_k(
    const float* __restrict__ in, const float* __restrict__ w,
    const float* __restrict__ bias, uint32_t* __restrict__ out,
    int IC, int IH, int IW, int OC, int OH, int OW, int K) {
    __shared__ float As[16][132];
    __shared__ float Bs[16][132];

    int tid = threadIdx.x;
    int tx = tid & 15, ty = tid >> 4;
    int pix0 = blockIdx.x * 128;
    int oc0 = blockIdx.y * 128;
    int ohw = OH * OW;
    int ihw = IH * IW;
    int nimg = pix0 / ohw;
    int rem0 = pix0 - nimg * ohw;
    const float* inN = in + (long long)nimg * IC * ihw;

    int pB = tid & 127;
    int kkB0 = (tid >> 7) * 8;
    int remB = rem0 + pB;
    int oh = remB / OW, ow = remB - oh * OW;
    int ih0 = oh * S - 1, iw0 = ow * S - 1;

    int kA = tid & 15;
    int mA = tid >> 4;

    unsigned long long acc[4][8];
#pragma unroll
    for (int i = 0; i < 4; i++)
#pragma unroll
        for (int j = 0; j < 8; j++) acc[i][j] = 0ull;

    for (int k0 = 0; k0 < K; k0 += 16) {
        {
            int k = k0 + kA;
            bool kin = (k < K);
#pragma unroll
            for (int u = 0; u < 8; u++) {
                int m = mA + u * 16;
                As[kA][m] = kin ? w[(oc0 + m) * K + k] : 0.0f;
            }
        }
#pragma unroll
        for (int u = 0; u < 8; u++) {
            int kk = kkB0 + u;
            int k = k0 + kk;
            float v = 0.0f;
            if (k < K) {
                int ic = k / 9;
                int r9 = k - ic * 9;
                int kh = r9 / 3;
                int kw = r9 - kh * 3;
                int ih = ih0 + kh, iw = iw0 + kw;
                if (ih >= 0 && ih < IH && iw >= 0 && iw < IW)
                    v = inN[ic * ihw + ih * IW + iw];
            }
            Bs[kk][pB] = v;
        }
        __syncthreads();
#pragma unroll
        for (int kk = 0; kk < 16; kk++) {
            ulonglong2 a01 = *(const ulonglong2*)&As[kk][ty * 4];
            ulonglong2 a23 = *(const ulonglong2*)&As[kk][64 + ty * 4];
            unsigned long long ap[4] = {a01.x, a01.y, a23.x, a23.y};
            float4 bA = *(const float4*)&Bs[kk][tx * 4];
            float4 bB = *(const float4*)&Bs[kk][64 + tx * 4];
            float bs[8] = {bA.x, bA.y, bA.z, bA.w, bB.x, bB.y, bB.z, bB.w};
            unsigned long long bb[8];
#pragma unroll
            for (int j = 0; j < 8; j++)
                PACK2(bb[j], __float_as_uint(bs[j]), __float_as_uint(bs[j]));
#pragma unroll
            for (int i = 0; i < 4; i++)
#pragma unroll
                for (int j = 0; j < 8; j++)
                    FMA2(acc[i][j], ap[i], bb[j], acc[i][j]);
        }
        __syncthreads();
    }

    uint32_t* outB = out + ((long long)nimg * OC + oc0) * ohw + rem0;
    int mrow[4] = {ty * 4, ty * 4 + 2, 64 + ty * 4, 64 + ty * 4 + 2};
#pragma unroll
    for (int i = 0; i < 4; i++) {
        int me = mrow[i];
        float be = bias[oc0 + me];
        float bo = bias[oc0 + me + 1];
        uint32_t* pe = outB + (long long)me * ohw;
        uint32_t* po = outB + (long long)(me + 1) * ohw;
#pragma unroll
        for (int g = 0; g < 2; g++) {
            uint4 ve, vo;
            unsigned int lo, hi;
            UNPACK2(lo, hi, acc[i][g * 4 + 0]);
            ve.x = packsplit(fmaxf(__uint_as_float(lo) + be, 0.0f));
            vo.x = packsplit(fmaxf(__uint_as_float(hi) + bo, 0.0f));
            UNPACK2(lo, hi, acc[i][g * 4 + 1]);
            ve.y = packsplit(fmaxf(__uint_as_float(lo) + be, 0.0f));
            vo.y = packsplit(fmaxf(__uint_as_float(hi) + bo, 0.0f));
            UNPACK2(lo, hi, acc[i][g * 4 + 2]);
            ve.z = packsplit(fmaxf(__uint_as_float(lo) + be, 0.0f));
            vo.z = packsplit(fmaxf(__uint_as_float(hi) + bo, 0.0f));
            UNPACK2(lo, hi, acc[i][g * 4 + 3]);
            ve.w = packsplit(fmaxf(__uint_as_float(lo) + be, 0.0f));
            vo.w = packsplit(fmaxf(__uint_as_float(hi) + bo, 0.0f));
            int off = tx * 4 + g * 64;
            *(uint4*)(pe + off) = ve;
            *(uint4*)(po + off) = vo;
        }
    }
}

// ---------------- pool + FC ------------------------------------------------
__global__ void pool_k(const float* __restrict__ in, float* __restrict__ out) {
    int warp = (blockIdx.x * blockDim.x + threadIdx.x) >> 5;
    int lane = threadIdx.x & 31;
    if (warp >= 64 * 512) return;
    const float* p = in + warp * 256;
    float s = 0.0f;
#pragma unroll
    for (int i = 0; i < 8; i++) s += p[lane + i * 32];
#pragma unroll
    for (int o = 16; o > 0; o >>= 1) s += __shfl_xor_sync(0xffffffffu, s, o);
    if (lane == 0) out[warp] = s * (1.0f / 256.0f);
}

__global__ void fc1_k(const float* __restrict__ inp, const float* __restrict__ w,
                      const float* __restrict__ b, float* __restrict__ out) {
    __shared__ float sx[512];
    int n = blockIdx.x;
    for (int i = threadIdx.x; i < 512; i += blockDim.x) sx[i] = inp[n * 512 + i];
    __syncthreads();
    int o = threadIdx.x;
    const float* wr = w + o * 512;
    float s = 0.0f;
#pragma unroll 8
    for (int k = 0; k < 512; k++) s += sx[k] * wr[k];
    s += b[o];
    out[n * 1024 + o] = s > 0.0f ? s : 0.0f;
}

__global__ void fc2_k(const float* __restrict__ inp, const float* __restrict__ w,
                      const float* __restrict__ b, float* __restrict__ out) {
    int idx = blockIdx.x * blockDim.x + threadIdx.x;
    if (idx >= 640) return;
    int n = idx / 10, o = idx - n * 10;
    const float* xr = inp + n * 1024;
    const float* wr = w + o * 1024;
    float s = 0.0f;
#pragma unroll 8
    for (int k = 0; k < 1024; k++) s += xr[k] * wr[k];
    out[idx] = s + b[o];
}

// ---------------- host orchestration ---------------------------------------
static inline int grid_for(int n) {
    int b = (n + 255) / 256;
    return b > 2048 ? 2048 : b;
}

static void run_select(const float* s, int n) {
    int j = n / 2;
    reset_k<<<1, 1024>>>();
    hist_k<<<grid_for(n), 256>>>(s, n);
    findbin_k<<<1, 32>>>(j);
    compact_k<<<grid_for(n), 256>>>(s, n);
    select_k<<<1, 1024>>>();
}

extern "C" void kernel_launch(void* const* d_in, const int* in_sizes, int n_in,
                              void* d_out, int out_size) {
    const float* x   = (const float*)d_in[0];
    const float* w1  = (const float*)d_in[1];
    const float* s1  = (const float*)d_in[2];
    const float* b1  = (const float*)d_in[3];
    const float* w2  = (const float*)d_in[4];
    const float* s2  = (const float*)d_in[5];
    const float* b2  = (const float*)d_in[6];
    const float* w3  = (const float*)d_in[7];
    const float* s3  = (const float*)d_in[8];
    const float* b3  = (const float*)d_in[9];
    const float* fw1 = (const float*)d_in[10];
    const float* fs1 = (const float*)d_in[11];
    const float* fb1 = (const float*)d_in[12];
    const float* fw2 = (const float*)d_in[13];
    const float* fs2 = (const float*)d_in[14];
    const float* fb2 = (const float*)d_in[15];
    float* out = (float*)d_out;

    uint32_t *h1p, *h2p, *mw2p, *mw3p;
    float *h3, *pool, *fc1o, *mw1, *mfw1, *mfw2;
    cudaGetSymbolAddress((void**)&h1p, g_h1p);
    cudaGetSymbolAddress((void**)&h2p, g_h2p);
    cudaGetSymbolAddress((void**)&h3, g_h3);
    cudaGetSymbolAddress((void**)&pool, g_pool);
    cudaGetSymbolAddress((void**)&fc1o, g_fc1);
    cudaGetSymbolAddress((void**)&mw1, g_mw1);
    cudaGetSymbolAddress((void**)&mw2p, g_mw2p);
    cudaGetSymbolAddress((void**)&mw3p, g_mw3p);
    cudaGetSymbolAddress((void**)&mfw1, g_mfw1);
    cudaGetSymbolAddress((void**)&mfw2, g_mfw2);

    cudaFuncSetAttribute(conv_mma_k<2, true>,
                         cudaFuncAttributeMaxDynamicSharedMemorySize, SM_CONV);
    cudaFuncSetAttribute(conv_mma_k<2, false>,
                         cudaFuncAttributeMaxDynamicSharedMemorySize, SM_CONV);

    // masks (exact stable-argsort semantics via 64-bit keys)
    run_select(s1, 128 * 27);
    mask_k<<<grid_for(128 * 27), 256>>>(w1, s1, mw1, 128 * 27);
    run_select(s2, 256 * 128 * 9);
    mask_pack_k<<<grid_for(256 * 128 * 9), 256>>>(w2, s2, mw2p, 128, 256 * 128 * 9);
    run_select(s3, 512 * 256 * 9);
    mask_pack_k<<<grid_for(512 * 256 * 9), 256>>>(w3, s3, mw3p, 256, 512 * 256 * 9);
    run_select(fs1, 1024 * 512);
    mask_k<<<grid_for(1024 * 512), 256>>>(fw1, fs1, mfw1, 1024 * 512);
    run_select(fs2, 10 * 1024);
    mask_k<<<grid_for(10 * 1024), 256>>>(fw2, fs2, mfw2, 10 * 1024);

    // conv1: [64,3,64,64] -> packed [64,128,64,64], stride 1 (SIMT)
    {
        dim3 g(64 * 64 * 64 / 128, 1);
        conv128_k<1><<<g, 256>>>(x, mw1, b1, h1p, 3, 64, 64, 128, 64, 64, 27);
    }
    // conv2: -> packed [64,256,32,32], stride 2 (HMMA bf16-split)
    {
        dim3 g(64 * 32 * 32 / 128, 1);
        conv_mma_k<2, true><<<g, 512, SM_CONV>>>(
            h1p, mw2p, b2, (void*)h2p, 128, 64, 64, 256, 32, 32, 128 * 9);
    }
    // conv3: -> fp32 [64,512,16,16], stride 2 (HMMA bf16-split)
    {
        dim3 g(64 * 16 * 16 / 128, 2);
        conv_mma_k<2, false><<<g, 512, SM_CONV>>>(
            h2p, mw3p, b3, (void*)h3, 256, 32, 32, 512, 16, 16, 256 * 9);
    }
    // global average pool -> [64,512]
    pool_k<<<(64 * 512) / 8, 256>>>(h3, pool);
    // fc1 -> [64,1024] relu
    fc1_k<<<64, 1024>>>(pool, mfw1, fb1, fc1o);
    // fc2 -> [64,10]
    fc2_k<<<3, 256>>>(fc1o, mfw2, fb2, out);
}

// round 9
// speedup vs baseline: 3.2185x; 1.6246x over previous
#include <cuda_runtime.h>
#include <cuda_bf16.h>
#include <cstdint>

// ---------------- static device buffers (no runtime allocation allowed) -----
__device__ __align__(16) uint32_t g_h1p[64 * 128 * 64 * 64]; // conv1 out, packed (lo<<16|hi) bf16
__device__ __align__(16) uint32_t g_h2p[64 * 256 * 32 * 32]; // conv2 out, packed
__device__ float g_h3[64 * 512 * 16 * 16];                   // conv3 out fp32
__device__ float g_pool[64 * 512];
__device__ float g_fc1[64 * 1024];

__device__ float g_mw1[128 * 3 * 9];                         // conv1 masked fp32
__device__ __align__(16) uint32_t g_mw2p[256 * 128 * 9];     // masked+reordered+packed
__device__ __align__(16) uint32_t g_mw3p[512 * 256 * 9];
__device__ float g_mfw1[1024 * 512];
__device__ float g_mfw2[10 * 1024];

// ---- batched selection state ----
// tensor sizes / offsets in the concatenated score stream
#define TN0 3456
#define TN1 294912
#define TN2 1179648
#define TN3 524288
#define TN4 10240
#define OFF1 3456
#define OFF2 298368
#define OFF3 1478016
#define OFF4 2002304
#define TOTSEL 2012544
#define SBUF (1 << 18)

__device__ uint32_t           g_hist5[5 * 1024];
__device__ int                g_cnt5[5];
__device__ int                g_selbin5[5];
__device__ int                g_selrank5[5];
__device__ unsigned long long g_thresh5[5];
__device__ unsigned long long g_bufA5[5 * SBUF];
__device__ unsigned long long g_bufB5[5 * SBUF];

// ---------------- packed f32x2 helpers (SIMT conv1) -------------------------
#define FMA2(d, a, b, c) \
    asm("fma.rn.f32x2 %0, %1, %2, %3;" : "=l"(d) : "l"(a), "l"(b), "l"(c))
#define PACK2(out, lo, hi) \
    asm("mov.b64 %0, {%1, %2};" : "=l"(out) : "r"(lo), "r"(hi))
#define UNPACK2(lo, hi, in) \
    asm("mov.b64 {%0, %1}, %2;" : "=r"(lo), "=r"(hi) : "l"(in))

// split fp32 -> packed word (lo16<<16)|hi16, bf16 hi + bf16 residual lo
__device__ __forceinline__ uint32_t packsplit(float v) {
    __nv_bfloat16 h = __float2bfloat16(v);
    float hf = __bfloat162float(h);
    __nv_bfloat16 l = __float2bfloat16(v - hf);
    uint16_t hb = *(uint16_t*)&h;
    uint16_t lb = *(uint16_t*)&l;
    return ((uint32_t)lb << 16) | (uint32_t)hb;
}

// ---------------- HMMA helpers ---------------------------------------------
__device__ __forceinline__ uint32_t smem_u32(const void* p) {
    uint32_t a;
    asm("{ .reg .u64 t; cvta.to.shared.u64 t, %1; cvt.u32.u64 %0, t; }"
        : "=r"(a) : "l"(p));
    return a;
}

__device__ __forceinline__ void ldm_x4(uint32_t* r, uint32_t addr) {
    asm volatile("ldmatrix.sync.aligned.m8n8.x4.shared.b16 {%0,%1,%2,%3}, [%4];"
                 : "=r"(r[0]), "=r"(r[1]), "=r"(r[2]), "=r"(r[3]) : "r"(addr));
}

__device__ __forceinline__ void mma_bf16(float* c, const uint32_t* a,
                                         const uint32_t* b) {
    asm volatile(
        "mma.sync.aligned.m16n8k16.row.col.f32.bf16.bf16.f32 "
        "{%0,%1,%2,%3}, {%4,%5,%6,%7}, {%8,%9}, {%0,%1,%2,%3};"
        : "+f"(c[0]), "+f"(c[1]), "+f"(c[2]), "+f"(c[3])
        : "r"(a[0]), "r"(a[1]), "r"(a[2]), "r"(a[3]), "r"(b[0]), "r"(b[1]));
}

// ---------------- batched mask selection ------------------------------------
// key64 = (bits(|s|) << 32) | local_index : stable-argsort-equivalent order.
// mask[i] = key64(i) >= (N/2-th smallest key64), per tensor.

__device__ __forceinline__ void sel_resolve(int i, int& t, int& li) {
    if (i < OFF1)      { t = 0; li = i; }
    else if (i < OFF2) { t = 1; li = i - OFF1; }
    else if (i < OFF3) { t = 2; li = i - OFF2; }
    else if (i < OFF4) { t = 3; li = i - OFF3; }
    else               { t = 4; li = i - OFF4; }
}

__global__ __launch_bounds__(1024) void bhist_k(
    const float* __restrict__ s0, const float* __restrict__ s1,
    const float* __restrict__ s2, const float* __restrict__ s3,
    const float* __restrict__ s4) {
    __shared__ uint32_t h[5120];
    for (int i = threadIdx.x; i < 5120; i += 1024) h[i] = 0;
    __syncthreads();
    const float* sp[5] = {s0, s1, s2, s3, s4};
    for (int i = blockIdx.x * 1024 + threadIdx.x; i < TOTSEL;
         i += gridDim.x * 1024) {
        int t, li;
        sel_resolve(i, t, li);
        uint32_t bits = __float_as_uint(sp[t][li]) & 0x7fffffffu;
        atomicAdd(&h[t * 1024 + (bits >> 21)], 1u);
    }
    __syncthreads();
    for (int i = threadIdx.x; i < 5120; i += 1024)
        if (h[i]) atomicAdd(&g_hist5[i], h[i]);
}

__global__ void bfind_k() {
    int t = threadIdx.x;
    if (t < 5) {
        const int jt[5] = {TN0 / 2, TN1 / 2, TN2 / 2, TN3 / 2, TN4 / 2};
        int j = jt[t], cum = 0;
        for (int b = 0; b < 1024; b++) {
            int c = (int)g_hist5[t * 1024 + b];
            if (j < cum + c) { g_selbin5[t] = b; g_selrank5[t] = j - cum; break; }
            cum += c;
        }
    }
}

__global__ __launch_bounds__(256) void bcompact_k(
    const float* __restrict__ s0, const float* __restrict__ s1,
    const float* __restrict__ s2, const float* __restrict__ s3,
    const float* __restrict__ s4) {
    const float* sp[5] = {s0, s1, s2, s3, s4};
    for (int i = blockIdx.x * 256 + threadIdx.x; i < TOTSEL;
         i += gridDim.x * 256) {
        int t, li;
        sel_resolve(i, t, li);
        uint32_t bits = __float_as_uint(sp[t][li]) & 0x7fffffffu;
        if ((int)(bits >> 21) == g_selbin5[t]) {
            int p = atomicAdd(&g_cnt5[t], 1);
            if (p < SBUF)
                g_bufA5[t * SBUF + p] =
                    ((unsigned long long)bits << 32) | (unsigned int)li;
        }
    }
}

// per-tensor radix select (5 blocks). byte 7 of the key is constant within a
// bin (bin = bits[30:21], byte7 = bits[30:24]) -> start at shift 48.
__global__ __launch_bounds__(1024) void bselect_k() {
    __shared__ int hist[256];
    __shared__ int s_m, s_r, s_d, s_cnt;
    int t = blockIdx.x;
    int tid = threadIdx.x;
    if (tid == 0) {
        int c = g_cnt5[t];
        s_m = c < SBUF ? c : SBUF;
        s_r = g_selrank5[t];
    }
    __syncthreads();
    unsigned long long* cur = g_bufA5 + (long long)t * SBUF;
    unsigned long long* nxt = g_bufB5 + (long long)t * SBUF;
    for (int shift = 48; shift >= 0; shift -= 8) {
        for (int b = tid; b < 256; b += blockDim.x) hist[b] = 0;
        __syncthreads();
        int m = s_m;
        for (int i = tid; i < m; i += blockDim.x)
            atomicAdd(&hist[(int)((cur[i] >> shift) & 255ull)], 1);
        __syncthreads();
        if (tid == 0) {
            int r = s_r, cum = 0;
            for (int d = 0; d < 256; d++) {
                int c = hist[d];
                if (r < cum + c) { s_d = d; s_r = r - cum; break; }
                cum += c;
            }
            s_cnt = 0;
        }
        __syncthreads();
        int d = s_d;
        for (int i = tid; i < m; i += blockDim.x) {
            unsigned long long v = cur[i];
            if ((int)((v >> shift) & 255ull) == d) {
                int p = atomicAdd(&s_cnt, 1);
                nxt[p] = v;
            }
        }
        __syncthreads();
        if (tid == 0) s_m = s_cnt;
        __syncthreads();
        unsigned long long* tmp = cur; cur = nxt; nxt = tmp;
    }
    if (tid == 0) g_thresh5[t] = cur[0];
}

// fused mask apply: plain fp32 for w1/fw1/fw2, reorder+split-pack for w2/w3
__global__ __launch_bounds__(256) void bmask_k(
    const float* __restrict__ s0, const float* __restrict__ s1,
    const float* __restrict__ s2, const float* __restrict__ s3,
    const float* __restrict__ s4,
    const float* __restrict__ w0, const float* __restrict__ w1,
    const float* __restrict__ w2, const float* __restrict__ w3,
    const float* __restrict__ w4,
    float* __restrict__ m0, uint32_t* __restrict__ m1p,
    uint32_t* __restrict__ m2p, float* __restrict__ m3,
    float* __restrict__ m4) {
    const float* sp[5] = {s0, s1, s2, s3, s4};
    const float* wp[5] = {w0, w1, w2, w3, w4};
    for (int i = blockIdx.x * 256 + threadIdx.x; i < TOTSEL;
         i += gridDim.x * 256) {
        int t, li;
        sel_resolve(i, t, li);
        uint32_t bits = __float_as_uint(sp[t][li]) & 0x7fffffffu;
        unsigned long long key =
            ((unsigned long long)bits << 32) | (unsigned int)li;
        float v = (key >= g_thresh5[t]) ? wp[t][li] : 0.0f;
        if (t == 0) m0[li] = v;
        else if (t == 3) m3[li] = v;
        else if (t == 4) m4[li] = v;
        else if (t == 1) {
            const int K = 128 * 9;
            int oc = li / K;
            int r = li - oc * K;
            int ic = r / 9;
            int tap = r - ic * 9;
            m1p[oc * K + tap * 128 + ic] = packsplit(v);
        } else {
            const int K = 256 * 9;
            int oc = li / K;
            int r = li - oc * K;
            int ic = r / 9;
            int tap = r - ic * 9;
            m2p[oc * K + tap * 256 + ic] = packsplit(v);
        }
    }
}

// ---------------- HMMA conv (conv2/conv3), double-buffered ------------------
// D[oc, pix] = sum_k' W[oc,k'] * im2col[pix,k'], k' = tap*IC + ic (tap-major).
// BM=256, BN=128 pixels, BK=32 (one tap per chunk). 512 threads = 16 warps,
// warp (mg=w&3, ng=w>>2) owns m64 x n32. 3 bf16 MMAs: hi*hi + hi*lo + lo*hi.
// Two smem stages; chunk k+1 LDGs issue before chunk k's MMA phase.
#define CBM 256
#define CBN 128
#define CBK 32
#define ROWB 80
#define AH_O 0
#define AL_O (CBM * ROWB)              // 20480
#define BH_O (2 * CBM * ROWB)          // 40960
#define BL_O (2 * CBM * ROWB + CBN * ROWB)
#define STG (2 * CBM * ROWB + 2 * CBN * ROWB)   // 61440
#define SM_CONV (2 * STG)                        // 122880

template <int S, bool PACKOUT>
__global__ __launch_bounds__(512, 1) void conv_mma_k(
    const uint32_t* __restrict__ in, const uint32_t* __restrict__ wp,
    const float* __restrict__ bias, void* __restrict__ outv,
    int IC, int IH, int IW, int OCt, int OH, int OW, int K) {
    extern __shared__ char smem[];
    uint32_t sm = smem_u32(smem);
    int tid = threadIdx.x;
    int wid = tid >> 5, lane = tid & 31;

    int pix0 = blockIdx.x * CBN;
    int oc0 = blockIdx.y * CBM;
    int ohw = OH * OW;
    int ihw = IH * IW;
    int nimg = pix0 / ohw;             // 128 | ohw
    int rem0 = pix0 - nimg * ohw;
    const uint32_t* inN = in + (long long)nimg * IC * ihw;

    int ocA = tid >> 1;
    int halfA = tid & 1;
    int pB = tid & 127;
    int icj = (tid >> 7) * 8;
    int remB = rem0 + pB;
    int oh = remB / OW, ow = remB - oh * OW;
    int ih0 = oh * S - 1, iw0 = ow * S - 1;

    int mg = wid & 3, ng = wid >> 2;

    float acc[4][4][4];
#pragma unroll
    for (int a = 0; a < 4; a++)
#pragma unroll
        for (int b = 0; b < 4; b++)
#pragma unroll
            for (int c = 0; c < 4; c++) acc[a][b][c] = 0.0f;

    uint4 av[4];         // staged A chunk (16 packed words)
    uint32_t wv[8];      // staged B chunk

    const uint4* aRow = (const uint4*)(wp + (long long)(oc0 + ocA) * K) + halfA * 4;

    auto gatherA = [&](int k0) {
        const uint4* src = aRow + (k0 >> 2);
#pragma unroll
        for (int q = 0; q < 4; q++) av[q] = src[q];
    };
    auto gatherB = [&](int k0) {
        int tap = k0 / IC;
        int icoff = k0 - tap * IC;
        int kh = tap / 3;
        int kw = tap - kh * 3;
        int ih = ih0 + kh, iw = iw0 + kw;
        bool valid = (ih >= 0 && ih < IH && iw >= 0 && iw < IW);
        if (valid) {
            const uint32_t* p = inN + (icoff + icj) * ihw + ih * IW + iw;
#pragma unroll
            for (int j = 0; j < 8; j++) { wv[j] = *p; p += ihw; }
        } else {
#pragma unroll
            for (int j = 0; j < 8; j++) wv[j] = 0u;
        }
    };
    auto storeAB = [&](int st) {
        uint32_t base = sm + st * STG;
        uint32_t arow = base + AH_O + ocA * ROWB + halfA * 32;
        uint32_t lrow = arow + (AL_O - AH_O);
#pragma unroll
        for (int q = 0; q < 4; q++) {
            uint32_t h01 = __byte_perm(av[q].x, av[q].y, 0x5410);
            uint32_t l01 = __byte_perm(av[q].x, av[q].y, 0x7632);
            uint32_t h23 = __byte_perm(av[q].z, av[q].w, 0x5410);
            uint32_t l23 = __byte_perm(av[q].z, av[q].w, 0x7632);
            asm volatile("st.shared.v2.b32 [%0], {%1,%2};"
                         :: "r"(arow + q * 8), "r"(h01), "r"(h23) : "memory");
            asm volatile("st.shared.v2.b32 [%0], {%1,%2};"
                         :: "r"(lrow + q * 8), "r"(l01), "r"(l23) : "memory");
        }
        uint32_t brow = base + BH_O + pB * ROWB + icj * 2;
        uint32_t blrow = brow + (BL_O - BH_O);
#pragma unroll
        for (int j = 0; j < 8; j += 4) {
            uint32_t h01 = __byte_perm(wv[j], wv[j + 1], 0x5410);
            uint32_t l01 = __byte_perm(wv[j], wv[j + 1], 0x7632);
            uint32_t h23 = __byte_perm(wv[j + 2], wv[j + 3], 0x5410);
            uint32_t l23 = __byte_perm(wv[j + 2], wv[j + 3], 0x7632);
            asm volatile("st.shared.v2.b32 [%0], {%1,%2};"
                         :: "r"(brow + j * 2), "r"(h01), "r"(h23) : "memory");
            asm volatile("st.shared.v2.b32 [%0], {%1,%2};"
                         :: "r"(blrow + j * 2), "r"(l01), "r"(l23) : "memory");
        }
    };

    // prologue: fill stage 0
    gatherA(0);
    gatherB(0);
    storeAB(0);
    __syncthreads();

    int st = 0;
    for (int k0 = 0; k0 < K; k0 += CBK) {
        bool more = (k0 + CBK) < K;
        if (more) {             // issue next chunk's LDGs before the MMA phase
            gatherA(k0 + CBK);
            gatherB(k0 + CBK);
        }

        uint32_t base = sm + st * STG;
#pragma unroll
        for (int s = 0; s < 2; s++) {
            uint32_t bh[4][2], bl[4][2];
#pragma unroll
            for (int p = 0; p < 2; p++) {
                int row = ng * 32 + p * 16 + (lane & 7) + ((lane >> 4) & 1) * 8;
                int col = s * 16 + ((lane >> 3) & 1) * 8;
                uint32_t addr = base + BH_O + row * ROWB + col * 2;
                uint32_t r[4];
                ldm_x4(r, addr);
                bh[p * 2][0] = r[0]; bh[p * 2][1] = r[1];
                bh[p * 2 + 1][0] = r[2]; bh[p * 2 + 1][1] = r[3];
                ldm_x4(r, addr + (BL_O - BH_O));
                bl[p * 2][0] = r[0]; bl[p * 2][1] = r[1];
                bl[p * 2 + 1][0] = r[2]; bl[p * 2 + 1][1] = r[3];
            }
#pragma unroll
            for (int mb = 0; mb < 4; mb++) {
                int row = mg * 64 + mb * 16 + (lane & 15);
                int col = s * 16 + (lane >> 4) * 8;
                uint32_t addr = base + AH_O + row * ROWB + col * 2;
                uint32_t ah[4], al[4];
                ldm_x4(ah, addr);
                ldm_x4(al, addr + (AL_O - AH_O));
#pragma unroll
                for (int nb = 0; nb < 4; nb++) {
                    mma_bf16(acc[mb][nb], ah, bh[nb]);
                    mma_bf16(acc[mb][nb], ah, bl[nb]);
                    mma_bf16(acc[mb][nb], al, bh[nb]);
                }
            }
        }

        if (more) storeAB(st ^ 1);
        __syncthreads();
        st ^= 1;
    }

    // ---- epilogue: bias + relu, write packed or fp32
    long long outbase = ((long long)nimg * OCt + oc0) * ohw + rem0;
#pragma unroll
    for (int mb = 0; mb < 4; mb++) {
        int r0 = mg * 64 + mb * 16 + (lane >> 2);
        int r1 = r0 + 8;
        float bv0 = bias[oc0 + r0];
        float bv1 = bias[oc0 + r1];
#pragma unroll
        for (int nb = 0; nb < 4; nb++) {
            int n = ng * 32 + nb * 8 + 2 * (lane & 3);
            float v00 = fmaxf(acc[mb][nb][0] + bv0, 0.0f);
            float v01 = fmaxf(acc[mb][nb][1] + bv0, 0.0f);
            float v10 = fmaxf(acc[mb][nb][2] + bv1, 0.0f);
            float v11 = fmaxf(acc[mb][nb][3] + bv1, 0.0f);
            if (PACKOUT) {
                uint32_t* o = (uint32_t*)outv;
                *(uint2*)(o + outbase + (long long)r0 * ohw + n) =
                    make_uint2(packsplit(v00), packsplit(v01));
                *(uint2*)(o + outbase + (long long)r1 * ohw + n) =
                    make_uint2(packsplit(v10), packsplit(v11));
            } else {
                float* o = (float*)outv;
                *(float2*)(o + outbase + (long long)r0 * ohw + n) = make_float2(v00, v01);
                *(float2*)(o + outbase + (long long)r1 * ohw + n) = make_float2(v10, v11);
            }
        }
    }
}

// ---------------- SIMT conv1, 128x128 tile, packed f32x2 FMA, packed out ----
template <int S>
__global__ __launch_bounds__(256, 2) void conv128_k(
    const float* __restrict__ in, const float* __restrict__ w,
    const float* __restrict__ bias, uint32_t* __restrict__ out,
    int IC, int IH, int IW, int OC, int OH, int OW, int K) {
    __shared__ float As[16][132];
    __shared__ float Bs[16][132];

    int tid = threadIdx.x;
    int tx = tid & 15, ty = tid >> 4;
    int pix0 = blockIdx.x * 128;
    int oc0 = blockIdx.y * 128;
    int ohw = OH * OW;
    int ihw = IH * IW;
    int nimg = pix0 / ohw;
    int rem0 = pix0 - nimg * ohw;
    const float* inN = in + (long long)nimg * IC * ihw;

    int pB = tid & 127;
    int kkB0 = (tid >> 7) * 8;
    int remB = rem0 + pB;
    int oh = remB / OW, ow = remB - oh * OW;
    int ih0 = oh * S - 1, iw0 = ow * S - 1;

    int kA = tid & 15;
    int mA = tid >> 4;

    unsigned long long acc[4][8];
#pragma unroll
    for (int i = 0; i < 4; i++)
#pragma unroll
        for (int j = 0; j < 8; j++) acc[i][j] = 0ull;

    for (int k0 = 0; k0 < K; k0 += 16) {
        {
            int k = k0 + kA;
            bool kin = (k < K);
#pragma unroll
            for (int u = 0; u < 8; u++) {
                int m = mA + u * 16;
                As[kA][m] = kin ? w[(oc0 + m) * K + k] : 0.0f;
            }
        }
#pragma unroll
        for (int u = 0; u < 8; u++) {
            int kk = kkB0 + u;
            int k = k0 + kk;
            float v = 0.0f;
            if (k < K) {
                int ic = k / 9;
                int r9 = k - ic * 9;
                int kh = r9 / 3;
                int kw = r9 - kh * 3;
                int ih = ih0 + kh, iw = iw0 + kw;
                if (ih >= 0 && ih < IH && iw >= 0 && iw < IW)
                    v = inN[ic * ihw + ih * IW + iw];
            }
            Bs[kk][pB] = v;
        }
        __syncthreads();
#pragma unroll
        for (int kk = 0; kk < 16; kk++) {
            ulonglong2 a01 = *(const ulonglong2*)&As[kk][ty * 4];
            ulonglong2 a23 = *(const ulonglong2*)&As[kk][64 + ty * 4];
            unsigned long long ap[4] = {a01.x, a01.y, a23.x, a23.y};
            float4 bA = *(const float4*)&Bs[kk][tx * 4];
            float4 bB = *(const float4*)&Bs[kk][64 + tx * 4];
            float bs[8] = {bA.x, bA.y, bA.z, bA.w, bB.x, bB.y, bB.z, bB.w};
            unsigned long long bb[8];
#pragma unroll
            for (int j = 0; j < 8; j++)
                PACK2(bb[j], __float_as_uint(bs[j]), __float_as_uint(bs[j]));
#pragma unroll
            for (int i = 0; i < 4; i++)
#pragma unroll
                for (int j = 0; j < 8; j++)
                    FMA2(acc[i][j], ap[i], bb[j], acc[i][j]);
        }
        __syncthreads();
    }

    uint32_t* outB = out + ((long long)nimg * OC + oc0) * ohw + rem0;
    int mrow[4] = {ty * 4, ty * 4 + 2, 64 + ty * 4, 64 + ty * 4 + 2};
#pragma unroll
    for (int i = 0; i < 4; i++) {
        int me = mrow[i];
        float be = bias[oc0 + me];
        float bo = bias[oc0 + me + 1];
        uint32_t* pe = outB + (long long)me * ohw;
        uint32_t* po = outB + (long long)(me + 1) * ohw;
#pragma unroll
        for (int g = 0; g < 2; g++) {
            uint4 ve, vo;
            unsigned int lo, hi;
            UNPACK2(lo, hi, acc[i][g * 4 + 0]);
            ve.x = packsplit(fmaxf(__uint_as_float(lo) + be, 0.0f));
            vo.x = packsplit(fmaxf(__uint_as_float(hi) + bo, 0.0f));
            UNPACK2(lo, hi, acc[i][g * 4 + 1]);
            ve.y = packsplit(fmaxf(__uint_as_float(lo) + be, 0.0f));
            vo.y = packsplit(fmaxf(__uint_as_float(hi) + bo, 0.0f));
            UNPACK2(lo, hi, acc[i][g * 4 + 2]);
            ve.z = packsplit(fmaxf(__uint_as_float(lo) + be, 0.0f));
            vo.z = packsplit(fmaxf(__uint_as_float(hi) + bo, 0.0f));
            UNPACK2(lo, hi, acc[i][g * 4 + 3]);
            ve.w = packsplit(fmaxf(__uint_as_float(lo) + be, 0.0f));
            vo.w = packsplit(fmaxf(__uint_as_float(hi) + bo, 0.0f));
            int off = tx * 4 + g * 64;
            *(uint4*)(pe + off) = ve;
            *(uint4*)(po + off) = vo;
        }
    }
}

// ---------------- pool + FC ------------------------------------------------
__global__ void pool_k(const float* __restrict__ in, float* __restrict__ out) {
    int warp = (blockIdx.x * blockDim.x + threadIdx.x) >> 5;
    int lane = threadIdx.x & 31;
    if (warp >= 64 * 512) return;
    const float* p = in + warp * 256;
    float s = 0.0f;
#pragma unroll
    for (int i = 0; i < 8; i++) s += p[lane + i * 32];
#pragma unroll
    for (int o = 16; o > 0; o >>= 1) s += __shfl_xor_sync(0xffffffffu, s, o);
    if (lane == 0) out[warp] = s * (1.0f / 256.0f);
}

__global__ void fc1_k(const float* __restrict__ inp, const float* __restrict__ w,
                      const float* __restrict__ b, float* __restrict__ out) {
    __shared__ float sx[512];
    int n = blockIdx.x;
    for (int i = threadIdx.x; i < 512; i += blockDim.x) sx[i] = inp[n * 512 + i];
    __syncthreads();
    int o = threadIdx.x;
    const float* wr = w + o * 512;
    float s = 0.0f;
#pragma unroll 8
    for (int k = 0; k < 512; k++) s += sx[k] * wr[k];
    s += b[o];
    out[n * 1024 + o] = s > 0.0f ? s : 0.0f;
}

__global__ void fc2_k(const float* __restrict__ inp, const float* __restrict__ w,
                      const float* __restrict__ b, float* __restrict__ out) {
    int idx = blockIdx.x * blockDim.x + threadIdx.x;
    if (idx >= 640) return;
    int n = idx / 10, o = idx - n * 10;
    const float* xr = inp + n * 1024;
    const float* wr = w + o * 1024;
    float s = 0.0f;
#pragma unroll 8
    for (int k = 0; k < 1024; k++) s += xr[k] * wr[k];
    out[idx] = s + b[o];
}

// ---------------- host orchestration ---------------------------------------
extern "C" void kernel_launch(void* const* d_in, const int* in_sizes, int n_in,
                              void* d_out, int out_size) {
    const float* x   = (const float*)d_in[0];
    const float* w1  = (const float*)d_in[1];
    const float* s1  = (const float*)d_in[2];
    const float* b1  = (const float*)d_in[3];
    const float* w2  = (const float*)d_in[4];
    const float* s2  = (const float*)d_in[5];
    const float* b2  = (const float*)d_in[6];
    const float* w3  = (const float*)d_in[7];
    const float* s3  = (const float*)d_in[8];
    const float* b3  = (const float*)d_in[9];
    const float* fw1 = (const float*)d_in[10];
    const float* fs1 = (const float*)d_in[11];
    const float* fb1 = (const float*)d_in[12];
    const float* fw2 = (const float*)d_in[13];
    const float* fs2 = (const float*)d_in[14];
    const float* fb2 = (const float*)d_in[15];
    float* out = (float*)d_out;

    uint32_t *h1p, *h2p, *mw2p, *mw3p;
    float *h3, *pool, *fc1o, *mw1, *mfw1, *mfw2;
    void *histA, *cntA;
    cudaGetSymbolAddress((void**)&h1p, g_h1p);
    cudaGetSymbolAddress((void**)&h2p, g_h2p);
    cudaGetSymbolAddress((void**)&h3, g_h3);
    cudaGetSymbolAddress((void**)&pool, g_pool);
    cudaGetSymbolAddress((void**)&fc1o, g_fc1);
    cudaGetSymbolAddress((void**)&mw1, g_mw1);
    cudaGetSymbolAddress((void**)&mw2p, g_mw2p);
    cudaGetSymbolAddress((void**)&mw3p, g_mw3p);
    cudaGetSymbolAddress((void**)&mfw1, g_mfw1);
    cudaGetSymbolAddress((void**)&mfw2, g_mfw2);
    cudaGetSymbolAddress(&histA, g_hist5);
    cudaGetSymbolAddress(&cntA, g_cnt5);

    cudaFuncSetAttribute(conv_mma_k<2, true>,
                         cudaFuncAttributeMaxDynamicSharedMemorySize, SM_CONV);
    cudaFuncSetAttribute(conv_mma_k<2, false>,
                         cudaFuncAttributeMaxDynamicSharedMemorySize, SM_CONV);

    // ---- batched selection: 2 memsets + 5 kernels total
    cudaMemsetAsync(histA, 0, 5 * 1024 * sizeof(uint32_t));
    cudaMemsetAsync(cntA, 0, 5 * sizeof(int));
    bhist_k<<<148, 1024>>>(s1, s2, s3, fs1, fs2);
    bfind_k<<<1, 32>>>();
    bcompact_k<<<2048, 256>>>(s1, s2, s3, fs1, fs2);
    bselect_k<<<5, 1024>>>();
    bmask_k<<<2048, 256>>>(s1, s2, s3, fs1, fs2,
                           w1, w2, w3, fw1, fw2,
                           mw1, mw2p, mw3p, mfw1, mfw2);

    // conv1: [64,3,64,64] -> packed [64,128,64,64], stride 1 (SIMT)
    {
        dim3 g(64 * 64 * 64 / 128, 1);
        conv128_k<1><<<g, 256>>>(x, mw1, b1, h1p, 3, 64, 64, 128, 64, 64, 27);
    }
    // conv2: -> packed [64,256,32,32], stride 2 (HMMA bf16-split, dbl-buffered)
    {
        dim3 g(64 * 32 * 32 / 128, 1);
        conv_mma_k<2, true><<<g, 512, SM_CONV>>>(
            h1p, mw2p, b2, (void*)h2p, 128, 64, 64, 256, 32, 32, 128 * 9);
    }
    // conv3: -> fp32 [64,512,16,16], stride 2 (HMMA bf16-split, dbl-buffered)
    {
        dim3 g(64 * 16 * 16 / 128, 2);
        conv_mma_k<2, false><<<g, 512, SM_CONV>>>(
            h2p, mw3p, b3, (void*)h3, 256, 32, 32, 512, 16, 16, 256 * 9);
    }
    // global average pool -> [64,512]
    pool_k<<<(64 * 512) / 8, 256>>>(h3, pool);
    // fc1 -> [64,1024] relu
    fc1_k<<<64, 1024>>>(pool, mfw1, fb1, fc1o);
    // fc2 -> [64,10]
    fc2_k<<<3, 256>>>(fc1o, mfw2, fb2, out);
}

// round 10
// speedup vs baseline: 3.2828x; 1.0200x over previous
#include <cuda_runtime.h>
#include <cuda_bf16.h>
#include <cstdint>

// ---------------- static device buffers (no runtime allocation allowed) -----
__device__ __align__(16) uint32_t g_h1p[64 * 128 * 64 * 64]; // conv1 out, packed (lo<<16|hi) bf16
__device__ __align__(16) uint32_t g_h2p[64 * 256 * 32 * 32]; // conv2 out, packed
__device__ float g_h3[64 * 512 * 16 * 16];                   // conv3 out fp32
__device__ float g_pool[64 * 512];
__device__ float g_fc1[64 * 1024];

__device__ __align__(16) uint32_t g_mw1p[128 * 32];          // conv1 masked, packed, tap-major, K padded 27->32
__device__ __align__(16) uint32_t g_mw2p[256 * 128 * 9];     // masked+reordered+packed
__device__ __align__(16) uint32_t g_mw3p[512 * 256 * 9];
__device__ float g_mfw1[1024 * 512];
__device__ float g_mfw2[10 * 1024];

// ---- batched selection state ----
#define TN0 3456
#define TN1 294912
#define TN2 1179648
#define TN3 524288
#define TN4 10240
#define OFF1 3456
#define OFF2 298368
#define OFF3 1478016
#define OFF4 2002304
#define TOTSEL 2012544
#define SBUF (1 << 18)

__device__ uint32_t           g_hist5[5 * 1024];
__device__ int                g_cnt5[5];
__device__ int                g_selbin5[5];
__device__ int                g_selrank5[5];
__device__ unsigned long long g_thresh5[5];
__device__ unsigned long long g_bufA5[5 * SBUF];
__device__ unsigned long long g_bufB5[5 * SBUF];

// ---------------- helpers ---------------------------------------------------
__device__ __forceinline__ uint32_t packsplit(float v) {
    __nv_bfloat16 h = __float2bfloat16(v);
    float hf = __bfloat162float(h);
    __nv_bfloat16 l = __float2bfloat16(v - hf);
    uint16_t hb = *(uint16_t*)&h;
    uint16_t lb = *(uint16_t*)&l;
    return ((uint32_t)lb << 16) | (uint32_t)hb;
}

__device__ __forceinline__ uint32_t smem_u32(const void* p) {
    uint32_t a;
    asm("{ .reg .u64 t; cvta.to.shared.u64 t, %1; cvt.u32.u64 %0, t; }"
        : "=r"(a) : "l"(p));
    return a;
}

__device__ __forceinline__ void ldm_x4(uint32_t* r, uint32_t addr) {
    asm volatile("ldmatrix.sync.aligned.m8n8.x4.shared.b16 {%0,%1,%2,%3}, [%4];"
                 : "=r"(r[0]), "=r"(r[1]), "=r"(r[2]), "=r"(r[3]) : "r"(addr));
}

__device__ __forceinline__ void mma_bf16(float* c, const uint32_t* a,
                                         const uint32_t* b) {
    asm volatile(
        "mma.sync.aligned.m16n8k16.row.col.f32.bf16.bf16.f32 "
        "{%0,%1,%2,%3}, {%4,%5,%6,%7}, {%8,%9}, {%0,%1,%2,%3};"
        : "+f"(c[0]), "+f"(c[1]), "+f"(c[2]), "+f"(c[3])
        : "r"(a[0]), "r"(a[1]), "r"(a[2]), "r"(a[3]), "r"(b[0]), "r"(b[1]));
}

// ---------------- batched mask selection ------------------------------------
__device__ __forceinline__ void sel_resolve(int i, int& t, int& li) {
    if (i < OFF1)      { t = 0; li = i; }
    else if (i < OFF2) { t = 1; li = i - OFF1; }
    else if (i < OFF3) { t = 2; li = i - OFF2; }
    else if (i < OFF4) { t = 3; li = i - OFF3; }
    else               { t = 4; li = i - OFF4; }
}

__global__ __launch_bounds__(1024) void bhist_k(
    const float* __restrict__ s0, const float* __restrict__ s1,
    const float* __restrict__ s2, const float* __restrict__ s3,
    const float* __restrict__ s4) {
    __shared__ uint32_t h[5120];
    for (int i = threadIdx.x; i < 5120; i += 1024) h[i] = 0;
    __syncthreads();
    const float* sp[5] = {s0, s1, s2, s3, s4};
    for (int i = blockIdx.x * 1024 + threadIdx.x; i < TOTSEL;
         i += gridDim.x * 1024) {
        int t, li;
        sel_resolve(i, t, li);
        uint32_t bits = __float_as_uint(sp[t][li]) & 0x7fffffffu;
        atomicAdd(&h[t * 1024 + (bits >> 21)], 1u);
    }
    __syncthreads();
    for (int i = threadIdx.x; i < 5120; i += 1024)
        if (h[i]) atomicAdd(&g_hist5[i], h[i]);
}

__global__ void bfind_k() {
    int t = threadIdx.x;
    if (t < 5) {
        const int jt[5] = {TN0 / 2, TN1 / 2, TN2 / 2, TN3 / 2, TN4 / 2};
        int j = jt[t], cum = 0;
        for (int b = 0; b < 1024; b++) {
            int c = (int)g_hist5[t * 1024 + b];
            if (j < cum + c) { g_selbin5[t] = b; g_selrank5[t] = j - cum; break; }
            cum += c;
        }
    }
}

__global__ __launch_bounds__(256) void bcompact_k(
    const float* __restrict__ s0, const float* __restrict__ s1,
    const float* __restrict__ s2, const float* __restrict__ s3,
    const float* __restrict__ s4) {
    const float* sp[5] = {s0, s1, s2, s3, s4};
    for (int i = blockIdx.x * 256 + threadIdx.x; i < TOTSEL;
         i += gridDim.x * 256) {
        int t, li;
        sel_resolve(i, t, li);
        uint32_t bits = __float_as_uint(sp[t][li]) & 0x7fffffffu;
        if ((int)(bits >> 21) == g_selbin5[t]) {
            int p = atomicAdd(&g_cnt5[t], 1);
            if (p < SBUF)
                g_bufA5[t * SBUF + p] =
                    ((unsigned long long)bits << 32) | (unsigned int)li;
        }
    }
}

// per-tensor radix select. keys unique -> early-exit when one survivor left.
__global__ __launch_bounds__(1024) void bselect_k() {
    __shared__ int hist[256];
    __shared__ int s_m, s_r, s_d, s_cnt;
    int t = blockIdx.x;
    int tid = threadIdx.x;
    if (tid == 0) {
        int c = g_cnt5[t];
        s_m = c < SBUF ? c : SBUF;
        s_r = g_selrank5[t];
    }
    __syncthreads();
    unsigned long long* cur = g_bufA5 + (long long)t * SBUF;
    unsigned long long* nxt = g_bufB5 + (long long)t * SBUF;
    for (int shift = 48; shift >= 0; shift -= 8) {
        for (int b = tid; b < 256; b += blockDim.x) hist[b] = 0;
        __syncthreads();
        int m = s_m;
        for (int i = tid; i < m; i += blockDim.x)
            atomicAdd(&hist[(int)((cur[i] >> shift) & 255ull)], 1);
        __syncthreads();
        if (tid == 0) {
            int r = s_r, cum = 0;
            for (int d = 0; d < 256; d++) {
                int c = hist[d];
                if (r < cum + c) { s_d = d; s_r = r - cum; break; }
                cum += c;
            }
            s_cnt = 0;
        }
        __syncthreads();
        int d = s_d;
        for (int i = tid; i < m; i += blockDim.x) {
            unsigned long long v = cur[i];
            if ((int)((v >> shift) & 255ull) == d) {
                int p = atomicAdd(&s_cnt, 1);
                nxt[p] = v;
            }
        }
        __syncthreads();
        if (tid == 0) s_m = s_cnt;
        __syncthreads();
        unsigned long long* tmp = cur; cur = nxt; nxt = tmp;
        if (s_m == 1) break;   // unique keys: survivor IS the j-th key
    }
    if (tid == 0) g_thresh5[t] = cur[0];
}

// fused mask apply. conv1 -> packed tap-major K=32-padded; conv2/3 -> packed
// tap-major; fc -> fp32.
__global__ __launch_bounds__(256) void bmask_k(
    const float* __restrict__ s0, const float* __restrict__ s1,
    const float* __restrict__ s2, const float* __restrict__ s3,
    const float* __restrict__ s4,
    const float* __restrict__ w0, const float* __restrict__ w1,
    const float* __restrict__ w2, const float* __restrict__ w3,
    const float* __restrict__ w4,
    uint32_t* __restrict__ m0p, uint32_t* __restrict__ m1p,
    uint32_t* __restrict__ m2p, float* __restrict__ m3,
    float* __restrict__ m4) {
    // zero the 5 pad columns (k'=27..31) of the conv1 packed weights
    int gz = blockIdx.x * 256 + threadIdx.x;
    if (gz < 128 * 5) {
        int oc = gz / 5;
        m0p[oc * 32 + 27 + (gz - oc * 5)] = 0u;
    }
    const float* sp[5] = {s0, s1, s2, s3, s4};
    const float* wp[5] = {w0, w1, w2, w3, w4};
    for (int i = blockIdx.x * 256 + threadIdx.x; i < TOTSEL;
         i += gridDim.x * 256) {
        int t, li;
        sel_resolve(i, t, li);
        uint32_t bits = __float_as_uint(sp[t][li]) & 0x7fffffffu;
        unsigned long long key =
            ((unsigned long long)bits << 32) | (unsigned int)li;
        float v = (key >= g_thresh5[t]) ? wp[t][li] : 0.0f;
        if (t == 0) {
            int oc = li / 27;
            int r = li - oc * 27;
            int ic = r / 9;
            int tap = r - ic * 9;
            m0p[oc * 32 + tap * 3 + ic] = packsplit(v);
        } else if (t == 3) m3[li] = v;
        else if (t == 4) m4[li] = v;
        else if (t == 1) {
            const int K = 128 * 9;
            int oc = li / K;
            int r = li - oc * K;
            int ic = r / 9;
            int tap = r - ic * 9;
            m1p[oc * K + tap * 128 + ic] = packsplit(v);
        } else {
            const int K = 256 * 9;
            int oc = li / K;
            int r = li - oc * K;
            int ic = r / 9;
            int tap = r - ic * 9;
            m2p[oc * K + tap * 256 + ic] = packsplit(v);
        }
    }
}

// ---------------- HMMA conv (conv2/conv3), double-buffered ------------------
#define CBM 256
#define CBN 128
#define CBK 32
#define ROWB 80
#define AH_O 0
#define AL_O (CBM * ROWB)
#define BH_O (2 * CBM * ROWB)
#define BL_O (2 * CBM * ROWB + CBN * ROWB)
#define STG (2 * CBM * ROWB + 2 * CBN * ROWB)   // 61440
#define SM_CONV (2 * STG)                        // 122880

template <int S, bool PACKOUT>
__global__ __launch_bounds__(512, 1) void conv_mma_k(
    const uint32_t* __restrict__ in, const uint32_t* __restrict__ wp,
    const float* __restrict__ bias, void* __restrict__ outv,
    int IC, int IH, int IW, int OCt, int OH, int OW, int K) {
    extern __shared__ char smem[];
    uint32_t sm = smem_u32(smem);
    int tid = threadIdx.x;
    int wid = tid >> 5, lane = tid & 31;

    int pix0 = blockIdx.x * CBN;
    int oc0 = blockIdx.y * CBM;
    int ohw = OH * OW;
    int ihw = IH * IW;
    int nimg = pix0 / ohw;
    int rem0 = pix0 - nimg * ohw;
    const uint32_t* inN = in + (long long)nimg * IC * ihw;

    int ocA = tid >> 1;
    int halfA = tid & 1;
    int pB = tid & 127;
    int icj = (tid >> 7) * 8;
    int remB = rem0 + pB;
    int oh = remB / OW, ow = remB - oh * OW;
    int ih0 = oh * S - 1, iw0 = ow * S - 1;

    int mg = wid & 3, ng = wid >> 2;

    float acc[4][4][4];
#pragma unroll
    for (int a = 0; a < 4; a++)
#pragma unroll
        for (int b = 0; b < 4; b++)
#pragma unroll
            for (int c = 0; c < 4; c++) acc[a][b][c] = 0.0f;

    uint4 av[4];
    uint32_t wv[8];

    const uint4* aRow = (const uint4*)(wp + (long long)(oc0 + ocA) * K) + halfA * 4;

    auto gatherA = [&](int k0) {
        const uint4* src = aRow + (k0 >> 2);
#pragma unroll
        for (int q = 0; q < 4; q++) av[q] = src[q];
    };
    auto gatherB = [&](int k0) {
        int tap = k0 / IC;
        int icoff = k0 - tap * IC;
        int kh = tap / 3;
        int kw = tap - kh * 3;
        int ih = ih0 + kh, iw = iw0 + kw;
        bool valid = (ih >= 0 && ih < IH && iw >= 0 && iw < IW);
        if (valid) {
            const uint32_t* p = inN + (icoff + icj) * ihw + ih * IW + iw;
#pragma unroll
            for (int j = 0; j < 8; j++) { wv[j] = *p; p += ihw; }
        } else {
#pragma unroll
            for (int j = 0; j < 8; j++) wv[j] = 0u;
        }
    };
    auto storeAB = [&](int st) {
        uint32_t base = sm + st * STG;
        uint32_t arow = base + AH_O + ocA * ROWB + halfA * 32;
        uint32_t lrow = arow + (AL_O - AH_O);
#pragma unroll
        for (int q = 0; q < 4; q++) {
            uint32_t h01 = __byte_perm(av[q].x, av[q].y, 0x5410);
            uint32_t l01 = __byte_perm(av[q].x, av[q].y, 0x7632);
            uint32_t h23 = __byte_perm(av[q].z, av[q].w, 0x5410);
            uint32_t l23 = __byte_perm(av[q].z, av[q].w, 0x7632);
            asm volatile("st.shared.v2.b32 [%0], {%1,%2};"
                         :: "r"(arow + q * 8), "r"(h01), "r"(h23) : "memory");
            asm volatile("st.shared.v2.b32 [%0], {%1,%2};"
                         :: "r"(lrow + q * 8), "r"(l01), "r"(l23) : "memory");
        }
        uint32_t brow = base + BH_O + pB * ROWB + icj * 2;
        uint32_t blrow = brow + (BL_O - BH_O);
#pragma unroll
        for (int j = 0; j < 8; j += 4) {
            uint32_t h01 = __byte_perm(wv[j], wv[j + 1], 0x5410);
            uint32_t l01 = __byte_perm(wv[j], wv[j + 1], 0x7632);
            uint32_t h23 = __byte_perm(wv[j + 2], wv[j + 3], 0x5410);
            uint32_t l23 = __byte_perm(wv[j + 2], wv[j + 3], 0x7632);
            asm volatile("st.shared.v2.b32 [%0], {%1,%2};"
                         :: "r"(brow + j * 2), "r"(h01), "r"(h23) : "memory");
            asm volatile("st.shared.v2.b32 [%0], {%1,%2};"
                         :: "r"(blrow + j * 2), "r"(l01), "r"(l23) : "memory");
        }
    };

    gatherA(0);
    gatherB(0);
    storeAB(0);
    __syncthreads();

    int st = 0;
    for (int k0 = 0; k0 < K; k0 += CBK) {
        bool more = (k0 + CBK) < K;
        if (more) {
            gatherA(k0 + CBK);
            gatherB(k0 + CBK);
        }

        uint32_t base = sm + st * STG;
#pragma unroll
        for (int s = 0; s < 2; s++) {
            uint32_t bh[4][2], bl[4][2];
#pragma unroll
            for (int p = 0; p < 2; p++) {
                int row = ng * 32 + p * 16 + (lane & 7) + ((lane >> 4) & 1) * 8;
                int col = s * 16 + ((lane >> 3) & 1) * 8;
                uint32_t addr = base + BH_O + row * ROWB + col * 2;
                uint32_t r[4];
                ldm_x4(r, addr);
                bh[p * 2][0] = r[0]; bh[p * 2][1] = r[1];
                bh[p * 2 + 1][0] = r[2]; bh[p * 2 + 1][1] = r[3];
                ldm_x4(r, addr + (BL_O - BH_O));
                bl[p * 2][0] = r[0]; bl[p * 2][1] = r[1];
                bl[p * 2 + 1][0] = r[2]; bl[p * 2 + 1][1] = r[3];
            }
#pragma unroll
            for (int mb = 0; mb < 4; mb++) {
                int row = mg * 64 + mb * 16 + (lane & 15);
                int col = s * 16 + (lane >> 4) * 8;
                uint32_t addr = base + AH_O + row * ROWB + col * 2;
                uint32_t ah[4], al[4];
                ldm_x4(ah, addr);
                ldm_x4(al, addr + (AL_O - AH_O));
#pragma unroll
                for (int nb = 0; nb < 4; nb++) {
                    mma_bf16(acc[mb][nb], ah, bh[nb]);
                    mma_bf16(acc[mb][nb], ah, bl[nb]);
                    mma_bf16(acc[mb][nb], al, bh[nb]);
                }
            }
        }

        if (more) storeAB(st ^ 1);
        __syncthreads();
        st ^= 1;
    }

    long long outbase = ((long long)nimg * OCt + oc0) * ohw + rem0;
#pragma unroll
    for (int mb = 0; mb < 4; mb++) {
        int r0 = mg * 64 + mb * 16 + (lane >> 2);
        int r1 = r0 + 8;
        float bv0 = bias[oc0 + r0];
        float bv1 = bias[oc0 + r1];
#pragma unroll
        for (int nb = 0; nb < 4; nb++) {
            int n = ng * 32 + nb * 8 + 2 * (lane & 3);
            float v00 = fmaxf(acc[mb][nb][0] + bv0, 0.0f);
            float v01 = fmaxf(acc[mb][nb][1] + bv0, 0.0f);
            float v10 = fmaxf(acc[mb][nb][2] + bv1, 0.0f);
            float v11 = fmaxf(acc[mb][nb][3] + bv1, 0.0f);
            if (PACKOUT) {
                uint32_t* o = (uint32_t*)outv;
                *(uint2*)(o + outbase + (long long)r0 * ohw + n) =
                    make_uint2(packsplit(v00), packsplit(v01));
                *(uint2*)(o + outbase + (long long)r1 * ohw + n) =
                    make_uint2(packsplit(v10), packsplit(v11));
            } else {
                float* o = (float*)outv;
                *(float2*)(o + outbase + (long long)r0 * ohw + n) = make_float2(v00, v01);
                *(float2*)(o + outbase + (long long)r1 * ohw + n) = make_float2(v10, v11);
            }
        }
    }
}

// ---------------- HMMA conv1: K=27 padded to 32, single chunk ---------------
// GEMM M=128 (oc), N=128 pixels/CTA, K'=32, fp32 input im2col'd + split in
// kernel. 512 threads = 16 warps; warp (mg=w&3, ng=w>>2) owns m32 x n32.
#define C1AH 0
#define C1AL (128 * ROWB)              // 10240
#define C1BH (2 * 128 * ROWB)          // 20480
#define C1BL (3 * 128 * ROWB)          // 30720
#define C1SM (4 * 128 * ROWB)          // 40960

__global__ __launch_bounds__(512, 2) void conv1_mma_k(
    const float* __restrict__ x, const uint32_t* __restrict__ wp,
    const float* __restrict__ bias, uint32_t* __restrict__ out) {
    __shared__ __align__(16) char smem[C1SM];
    uint32_t sm = smem_u32(smem);
    int tid = threadIdx.x;
    int wid = tid >> 5, lane = tid & 31;

    int pix0 = blockIdx.x * 128;
    int nimg = pix0 >> 12;             // ohw = 4096
    int rem0 = pix0 & 4095;

    // ---- A fill: 128 oc x 32 k packed words, 8 per thread
    {
        int ocA = tid >> 2;
        int kg = tid & 3;              // 8-word group
        const uint4* src = (const uint4*)(wp + ocA * 32 + kg * 8);
        uint32_t arow = sm + C1AH + ocA * ROWB + kg * 16;
        uint32_t lrow = arow + (C1AL - C1AH);
#pragma unroll
        for (int q = 0; q < 2; q++) {
            uint4 v = src[q];
            uint32_t h01 = __byte_perm(v.x, v.y, 0x5410);
            uint32_t l01 = __byte_perm(v.x, v.y, 0x7632);
            uint32_t h23 = __byte_perm(v.z, v.w, 0x5410);
            uint32_t l23 = __byte_perm(v.z, v.w, 0x7632);
            asm volatile("st.shared.v2.b32 [%0], {%1,%2};"
                         :: "r"(arow + q * 8), "r"(h01), "r"(h23) : "memory");
            asm volatile("st.shared.v2.b32 [%0], {%1,%2};"
                         :: "r"(lrow + q * 8), "r"(l01), "r"(l23) : "memory");
        }
    }
    // ---- B fill: im2col of fp32 x, k' = tap*3 + ic, 8 k per thread
    {
        int pB = tid & 127;
        int kj = (tid >> 7) * 8;
        int remB = rem0 + pB;
        int oh = remB >> 6, ow = remB & 63;
        const float* xN = x + (long long)nimg * 3 * 4096;
        uint32_t wvp[8];
#pragma unroll
        for (int j = 0; j < 8; j++) {
            int kq = kj + j;
            float v = 0.0f;
            if (kq < 27) {
                int tap = kq / 3;
                int ic = kq - tap * 3;
                int kh = tap / 3;
                int kw = tap - kh * 3;
                int ih = oh - 1 + kh, iw = ow - 1 + kw;
                if (ih >= 0 && ih < 64 && iw >= 0 && iw < 64)
                    v = xN[ic * 4096 + ih * 64 + iw];
            }
            wvp[j] = packsplit(v);
        }
        uint32_t brow = sm + C1BH + pB * ROWB + kj * 2;
        uint32_t blrow = brow + (C1BL - C1BH);
#pragma unroll
        for (int j = 0; j < 8; j += 4) {
            uint32_t h01 = __byte_perm(wvp[j], wvp[j + 1], 0x5410);
            uint32_t l01 = __byte_perm(wvp[j], wvp[j + 1], 0x7632);
            uint32_t h23 = __byte_perm(wvp[j + 2], wvp[j + 3], 0x5410);
            uint32_t l23 = __byte_perm(wvp[j + 2], wvp[j + 3], 0x7632);
            asm volatile("st.shared.v2.b32 [%0], {%1,%2};"
                         :: "r"(brow + j * 2), "r"(h01), "r"(h23) : "memory");
            asm volatile("st.shared.v2.b32 [%0], {%1,%2};"
                         :: "r"(blrow + j * 2), "r"(l01), "r"(l23) : "memory");
        }
    }
    __syncthreads();

    int mg = wid & 3, ng = wid >> 2;
    float acc[2][4][4];
#pragma unroll
    for (int a = 0; a < 2; a++)
#pragma unroll
        for (int b = 0; b < 4; b++)
#pragma unroll
            for (int c = 0; c < 4; c++) acc[a][b][c] = 0.0f;

#pragma unroll
    for (int s = 0; s < 2; s++) {
        uint32_t bh[4][2], bl[4][2];
#pragma unroll
        for (int p = 0; p < 2; p++) {
            int row = ng * 32 + p * 16 + (lane & 7) + ((lane >> 4) & 1) * 8;
            int col = s * 16 + ((lane >> 3) & 1) * 8;
            uint32_t addr = sm + C1BH + row * ROWB + col * 2;
            uint32_t r[4];
            ldm_x4(r, addr);
            bh[p * 2][0] = r[0]; bh[p * 2][1] = r[1];
            bh[p * 2 + 1][0] = r[2]; bh[p * 2 + 1][1] = r[3];
            ldm_x4(r, addr + (C1BL - C1BH));
            bl[p * 2][0] = r[0]; bl[p * 2][1] = r[1];
            bl[p * 2 + 1][0] = r[2]; bl[p * 2 + 1][1] = r[3];
        }
#pragma unroll
        for (int mb = 0; mb < 2; mb++) {
            int row = mg * 32 + mb * 16 + (lane & 15);
            int col = s * 16 + (lane >> 4) * 8;
            uint32_t addr = sm + C1AH + row * ROWB + col * 2;
            uint32_t ah[4], al[4];
            ldm_x4(ah, addr);
            ldm_x4(al, addr + (C1AL - C1AH));
#pragma unroll
            for (int nb = 0; nb < 4; nb++) {
                mma_bf16(acc[mb][nb], ah, bh[nb]);
                mma_bf16(acc[mb][nb], ah, bl[nb]);
                mma_bf16(acc[mb][nb], al, bh[nb]);
            }
        }
    }

    long long outbase = (long long)nimg * 128 * 4096 + rem0;
#pragma unroll
    for (int mb = 0; mb < 2; mb++) {
        int r0 = mg * 32 + mb * 16 + (lane >> 2);
        int r1 = r0 + 8;
        float bv0 = bias[r0];
        float bv1 = bias[r1];
#pragma unroll
        for (int nb = 0; nb < 4; nb++) {
            int n = ng * 32 + nb * 8 + 2 * (lane & 3);
            float v00 = fmaxf(acc[mb][nb][0] + bv0, 0.0f);
            float v01 = fmaxf(acc[mb][nb][1] + bv0, 0.0f);
            float v10 = fmaxf(acc[mb][nb][2] + bv1, 0.0f);
            float v11 = fmaxf(acc[mb][nb][3] + bv1, 0.0f);
            *(uint2*)(out + outbase + (long long)r0 * 4096 + n) =
                make_uint2(packsplit(v00), packsplit(v01));
            *(uint2*)(out + outbase + (long long)r1 * 4096 + n) =
                make_uint2(packsplit(v10), packsplit(v11));
        }
    }
}

// ---------------- pool + FC ------------------------------------------------
__global__ void pool_k(const float* __restrict__ in, float* __restrict__ out) {
    int warp = (blockIdx.x * blockDim.x + threadIdx.x) >> 5;
    int lane = threadIdx.x & 31;
    if (warp >= 64 * 512) return;
    const float* p = in + warp * 256;
    float s = 0.0f;
#pragma unroll
    for (int i = 0; i < 8; i++) s += p[lane + i * 32];
#pragma unroll
    for (int o = 16; o > 0; o >>= 1) s += __shfl_xor_sync(0xffffffffu, s, o);
    if (lane == 0) out[warp] = s * (1.0f / 256.0f);
}

__global__ void fc1_k(const float* __restrict__ inp, const float* __restrict__ w,
                      const float* __restrict__ b, float* __restrict__ out) {
    __shared__ float sx[512];
    int n = blockIdx.x;
    for (int i = threadIdx.x; i < 512; i += blockDim.x) sx[i] = inp[n * 512 + i];
    __syncthreads();
    int o = threadIdx.x;
    const float* wr = w + o * 512;
    float s = 0.0f;
#pragma unroll 8
    for (int k = 0; k < 512; k++) s += sx[k] * wr[k];
    s += b[o];
    out[n * 1024 + o] = s > 0.0f ? s : 0.0f;
}

__global__ void fc2_k(const float* __restrict__ inp, const float* __restrict__ w,
                      const float* __restrict__ b, float* __restrict__ out) {
    int idx = blockIdx.x * blockDim.x + threadIdx.x;
    if (idx >= 640) return;
    int n = idx / 10, o = idx - n * 10;
    const float* xr = inp + n * 1024;
    const float* wr = w + o * 1024;
    float s = 0.0f;
#pragma unroll 8
    for (int k = 0; k < 1024; k++) s += xr[k] * wr[k];
    out[idx] = s + b[o];
}

// ---------------- host orchestration ---------------------------------------
extern "C" void kernel_launch(void* const* d_in, const int* in_sizes, int n_in,
                              void* d_out, int out_size) {
    const float* x   = (const float*)d_in[0];
    const float* w1  = (const float*)d_in[1];
    const float* s1  = (const float*)d_in[2];
    const float* b1  = (const float*)d_in[3];
    const float* w2  = (const float*)d_in[4];
    const float* s2  = (const float*)d_in[5];
    const float* b2  = (const float*)d_in[6];
    const float* w3  = (const float*)d_in[7];
    const float* s3  = (const float*)d_in[8];
    const float* b3  = (const float*)d_in[9];
    const float* fw1 = (const float*)d_in[10];
    const float* fs1 = (const float*)d_in[11];
    const float* fb1 = (const float*)d_in[12];
    const float* fw2 = (const float*)d_in[13];
    const float* fs2 = (const float*)d_in[14];
    const float* fb2 = (const float*)d_in[15];
    float* out = (float*)d_out;

    uint32_t *h1p, *h2p, *mw1p, *mw2p, *mw3p;
    float *h3, *pool, *fc1o, *mfw1, *mfw2;
    void *histA, *cntA;
    cudaGetSymbolAddress((void**)&h1p, g_h1p);
    cudaGetSymbolAddress((void**)&h2p, g_h2p);
    cudaGetSymbolAddress((void**)&h3, g_h3);
    cudaGetSymbolAddress((void**)&pool, g_pool);
    cudaGetSymbolAddress((void**)&fc1o, g_fc1);
    cudaGetSymbolAddress((void**)&mw1p, g_mw1p);
    cudaGetSymbolAddress((void**)&mw2p, g_mw2p);
    cudaGetSymbolAddress((void**)&mw3p, g_mw3p);
    cudaGetSymbolAddress((void**)&mfw1, g_mfw1);
    cudaGetSymbolAddress((void**)&mfw2, g_mfw2);
    cudaGetSymbolAddress(&histA, g_hist5);
    cudaGetSymbolAddress(&cntA, g_cnt5);

    cudaFuncSetAttribute(conv_mma_k<2, true>,
                         cudaFuncAttributeMaxDynamicSharedMemorySize, SM_CONV);
    cudaFuncSetAttribute(conv_mma_k<2, false>,
                         cudaFuncAttributeMaxDynamicSharedMemorySize, SM_CONV);

    // ---- batched selection
    cudaMemsetAsync(histA, 0, 5 * 1024 * sizeof(uint32_t));
    cudaMemsetAsync(cntA, 0, 5 * sizeof(int));
    bhist_k<<<148, 1024>>>(s1, s2, s3, fs1, fs2);
    bfind_k<<<1, 32>>>();
    bcompact_k<<<2048, 256>>>(s1, s2, s3, fs1, fs2);
    bselect_k<<<5, 1024>>>();
    bmask_k<<<2048, 256>>>(s1, s2, s3, fs1, fs2,
                           w1, w2, w3, fw1, fw2,
                           mw1p, mw2p, mw3p, mfw1, mfw2);

    // conv1: [64,3,64,64] -> packed [64,128,64,64], stride 1 (HMMA, K=32 pad)
    conv1_mma_k<<<2048, 512>>>(x, mw1p, b1, h1p);
    // conv2: -> packed [64,256,32,32], stride 2 (HMMA, dbl-buffered)
    {
        dim3 g(64 * 32 * 32 / 128, 1);
        conv_mma_k<2, true><<<g, 512, SM_CONV>>>(
            h1p, mw2p, b2, (void*)h2p, 128, 64, 64, 256, 32, 32, 128 * 9);
    }
    // conv3: -> fp32 [64,512,16,16], stride 2 (HMMA, dbl-buffered)
    {
        dim3 g(64 * 16 * 16 / 128, 2);
        conv_mma_k<2, false><<<g, 512, SM_CONV>>>(
            h2p, mw3p, b3, (void*)h3, 256, 32, 32, 512, 16, 16, 256 * 9);
    }
    // global average pool -> [64,512]
    pool_k<<<(64 * 512) / 8, 256>>>(h3, pool);
    // fc1 -> [64,1024] relu
    fc1_k<<<64, 1024>>>(pool, mfw1, fb1, fc1o);
    // fc2 -> [64,10]
    fc2_k<<<3, 256>>>(fc1o, mfw2, fb2, out);
}